// round 8
// baseline (speedup 1.0000x reference)
#include <cuda_runtime.h>
#include <cuda_bf16.h>
#include <math.h>
#include <stdint.h>

#define NN 50000
#define NE 1600000
#define DD 128
#define OO 64

typedef __nv_bfloat16 bf16;
typedef __nv_bfloat162 bf162;

// ---------------- device scratch ----------------
__device__ int   g_is64;
__device__ int   g_deg[NN];
__device__ float g_dinv[NN];
__device__ float g_sinv[NN];
__device__ float g_as[NN];
__device__ float g_ad[NN];
__device__ int   g_rowptr[NN + 1];
__device__ int   g_cur[NN];
__device__ int   g_csr[NE];
__device__ float g_t[(size_t)NN * DD];
__device__ float g_agg[(size_t)NN * DD];
// split-bf16 feature buffers
__device__ bf16  g_p0h[(size_t)NN * DD];
__device__ bf16  g_p0l[(size_t)NN * DD];
__device__ bf16  g_p1h[(size_t)NN * DD];
__device__ bf16  g_p1l[(size_t)NN * DD];
__device__ bf16  g_p2h[(size_t)NN * DD];
__device__ bf16  g_p2l[(size_t)NN * DD];
// split + transposed weights: [n][k], k=128
#define WOFF_W1 0
#define WOFF_WL 16384
#define WOFF_WR 32768
#define WOFF_WG 49152
#define WOFF_WO 65536
#define WTOT    73728
__device__ bf16  g_wh[WTOT];
__device__ bf16  g_wl[WTOT];

__device__ __forceinline__ float leaky(float v) { return v > 0.f ? v : 0.2f * v; }

__device__ __forceinline__ void edge_ld(const void* ei, int e, int& s, int& d) {
    if (g_is64) {
        const long long* p = (const long long*)ei;
        s = (int)p[e]; d = (int)p[NE + e];
    } else {
        const int* p = (const int*)ei;
        s = p[e]; d = p[NE + e];
    }
}

__device__ __forceinline__ void split2(float x, float y, bf162& hi, bf162& lo) {
    hi = __float22bfloat162_rn(make_float2(x, y));
    lo = __float22bfloat162_rn(make_float2(x - __bfloat162float(hi.x),
                                           y - __bfloat162float(hi.y)));
}

__device__ __forceinline__ void st_split4(bf16* h, bf16* l, size_t base, float4 v) {
    bf162 h0, l0, h1, l1;
    split2(v.x, v.y, h0, l0);
    split2(v.z, v.w, h1, l1);
    *(bf162*)&h[base] = h0; *(bf162*)&h[base + 2] = h1;
    *(bf162*)&l[base] = l0; *(bf162*)&l[base + 2] = l1;
}

__device__ __forceinline__ float4 ld_split4(const bf16* __restrict__ h,
                                            const bf16* __restrict__ l, size_t base) {
    bf162 h0 = *(const bf162*)&h[base];
    bf162 h1 = *(const bf162*)&h[base + 2];
    bf162 l0 = *(const bf162*)&l[base];
    bf162 l1 = *(const bf162*)&l[base + 2];
    float4 r;
    r.x = __bfloat162float(h0.x) + __bfloat162float(l0.x);
    r.y = __bfloat162float(h0.y) + __bfloat162float(l0.y);
    r.z = __bfloat162float(h1.x) + __bfloat162float(l1.x);
    r.w = __bfloat162float(h1.y) + __bfloat162float(l1.y);
    return r;
}

// ---------------- setup ----------------
// detect + zero deg, one kernel
__global__ void k_detect_zero(const long long* ei) {
    int i = blockIdx.x * blockDim.x + threadIdx.x;
    if (i == 0) {
        bool is64 = true;
        for (int q = 0; q < 64; q++) {
            long long v = ei[q];
            if (v < 0 || v >= NN) { is64 = false; break; }
        }
        g_is64 = is64 ? 1 : 0;
    }
    if (i < NN) g_deg[i] = 0;
}

__global__ void k_deg(const void* ei) {
    int e = blockIdx.x * blockDim.x + threadIdx.x;
    if (e >= NE) return;
    int s, d; edge_ld(ei, e, s, d);
    atomicAdd(&g_deg[d], 1);
}

// scan + per-node scale factors, single block
__global__ void __launch_bounds__(1024) k_scan_scal() {
    __shared__ int sh[1024];
    __shared__ int sh_carry;
    int tid = threadIdx.x;
    if (tid == 0) { sh_carry = 0; g_rowptr[0] = 0; }
    __syncthreads();
    for (int base = 0; base < NN; base += 1024) {
        int i = base + tid;
        int v = (i < NN) ? g_deg[i] : 0;
        sh[tid] = v;
        __syncthreads();
#pragma unroll
        for (int off = 1; off < 1024; off <<= 1) {
            int t = (tid >= off) ? sh[tid - off] : 0;
            __syncthreads();
            sh[tid] += t;
            __syncthreads();
        }
        int carry = sh_carry;
        if (i < NN) {
            int excl = carry + sh[tid] - v;
            g_rowptr[i + 1] = carry + sh[tid];
            g_cur[i] = excl;
            g_dinv[i] = rsqrtf((float)(v + 1));
            g_sinv[i] = 1.0f / (float)max(v, 1);
        }
        __syncthreads();
        if (tid == 0) sh_carry = carry + sh[1023];
        __syncthreads();
    }
}

__global__ void k_fill(const void* ei) {
    int e = blockIdx.x * blockDim.x + threadIdx.x;
    if (e >= NE) return;
    int s, d; edge_ld(ei, e, s, d);
    int pos = atomicAdd(&g_cur[d], 1);
    g_csr[pos] = s;
}

// ---------------- merged one-shot prep: split 5 weights (transposed) + x ----------------
__global__ void k_prep(const float* __restrict__ W1, const float* __restrict__ Wl,
                       const float* __restrict__ Wr, const float* __restrict__ Wg,
                       const float* __restrict__ Wo, const float* __restrict__ x,
                       bf16* __restrict__ wh, bf16* __restrict__ wlo,
                       bf16* __restrict__ xh, bf16* __restrict__ xl) {
    int i = blockIdx.x * blockDim.x + threadIdx.x;
    if (i < WTOT) {
        const float* src; int N, off, li;
        if (i < 65536) {
            int w = i >> 14; li = i & 16383; off = w << 14; N = 128;
            src = (w == 0) ? W1 : (w == 1) ? Wl : (w == 2) ? Wr : Wg;
        } else {
            li = i - 65536; off = 65536; N = 64; src = Wo;
        }
        int k = li / N, n = li % N;
        float v = src[li];
        bf16 hi = __float2bfloat16_rn(v);
        wh[off + n * 128 + k] = hi;
        wlo[off + n * 128 + k] = __float2bfloat16_rn(v - __bfloat162float(hi));
    } else {
        int j = i - WTOT;                       // float4 index into x
        if (j < NN * DD / 4) {
            float4 v = ((const float4*)x)[j];
            st_split4(xh, xl, (size_t)j * 4, v);
        }
    }
}

// ---------------- tensor-core GEMM on pre-split bf16 ----------------
__device__ __forceinline__ void mma16816(float* c, const uint32_t* a, const uint32_t* b) {
    asm volatile(
        "mma.sync.aligned.m16n8k16.row.col.f32.bf16.bf16.f32 "
        "{%0,%1,%2,%3}, {%4,%5,%6,%7}, {%8,%9}, {%0,%1,%2,%3};"
        : "+f"(c[0]), "+f"(c[1]), "+f"(c[2]), "+f"(c[3])
        : "r"(a[0]), "r"(a[1]), "r"(a[2]), "r"(a[3]), "r"(b[0]), "r"(b[1]));
}

// C[NN x BN] = A@B^T (+A2@B2) (+bias)(relu). OSPLIT: bf16 hi/lo out. ALPHA: also
// compute per-row dots with a_s/a_d into g_as/g_ad (BN==128 only).
template<int BN, bool TWO, bool BIAS, bool RELU, bool OSPLIT, bool ALPHA>
__global__ void __launch_bounds__(256) k_gemm_bf(
        const bf16* __restrict__ A1h, const bf16* __restrict__ A1l,
        const bf16* __restrict__ A2h, const bf16* __restrict__ A2l,
        const bf16* __restrict__ B1h, const bf16* __restrict__ B1l,
        const bf16* __restrict__ B2h, const bf16* __restrict__ B2l,
        float* __restrict__ C, bf16* __restrict__ Ch, bf16* __restrict__ Cl,
        const float* __restrict__ bias,
        const float* __restrict__ avs, const float* __restrict__ avd) {
    constexpr int BM = 128, BK = 32, LD = 40;
    constexpr int MWARPS = (BN == 128) ? 2 : 4;
    constexpr int MW = BM / MWARPS;
    constexpr int MT = MW / 16;
    constexpr int NT = 4;

    __shared__ bf16 Ah[BM][LD];
    __shared__ bf16 Al[BM][LD];
    __shared__ bf16 Bh[BN][LD];
    __shared__ bf16 Bl[BN][LD];
    __shared__ float s_as[ALPHA ? BM : 1];
    __shared__ float s_ad[ALPHA ? BM : 1];
    __shared__ float s_avs[ALPHA ? BN : 1];
    __shared__ float s_avd[ALPHA ? BN : 1];

    const int tid = threadIdx.x;
    const int wid = tid >> 5;
    const int lane = tid & 31;
    const int g = lane >> 2;
    const int t = lane & 3;
    const int wm = wid % MWARPS;
    const int wn = wid / MWARPS;
    const int m0 = blockIdx.x * BM;
    const int m0w = wm * MW;
    const int n0w = wn * 32;

    if (ALPHA && tid < BM) {
        s_as[tid] = 0.f; s_ad[tid] = 0.f;
        s_avs[tid] = avs[tid]; s_avd[tid] = avd[tid];
    }

    float c[MT][NT][4];
#pragma unroll
    for (int i = 0; i < MT; i++)
#pragma unroll
        for (int j = 0; j < NT; j++)
#pragma unroll
            for (int q = 0; q < 4; q++) c[i][j][q] = 0.f;

    const int NPH = TWO ? 2 : 1;
    for (int ph = 0; ph < NPH; ph++) {
        const bf16* Aph = (TWO && ph) ? A2h : A1h;
        const bf16* Apl = (TWO && ph) ? A2l : A1l;
        const bf16* Bph = (TWO && ph) ? B2h : B1h;
        const bf16* Bpl = (TWO && ph) ? B2l : B1l;
#pragma unroll
        for (int k0 = 0; k0 < DD; k0 += BK) {
#pragma unroll
            for (int l = 0; l < 2; l++) {
                int idx = tid + l * 256;
                int m = idx >> 2;
                int ko = (idx & 3) * 8;
                int gr = m0 + m;
                uint4 vh = make_uint4(0, 0, 0, 0), vl = make_uint4(0, 0, 0, 0);
                if (gr < NN) {
                    vh = *(const uint4*)&Aph[(size_t)gr * DD + k0 + ko];
                    vl = *(const uint4*)&Apl[(size_t)gr * DD + k0 + ko];
                }
                *(uint4*)&Ah[m][ko] = vh;
                *(uint4*)&Al[m][ko] = vl;
            }
            constexpr int NB = (BN * BK) / (8 * 256);
#pragma unroll
            for (int l = 0; l < NB; l++) {
                int idx = tid + l * 256;
                int n = idx >> 2;
                int ko = (idx & 3) * 8;
                *(uint4*)&Bh[n][ko] = *(const uint4*)&Bph[(size_t)n * DD + k0 + ko];
                *(uint4*)&Bl[n][ko] = *(const uint4*)&Bpl[(size_t)n * DD + k0 + ko];
            }
            __syncthreads();
#pragma unroll
            for (int s = 0; s < 2; s++) {
                const int kb = s * 16;
                uint32_t bh[NT][2], bl[NT][2];
#pragma unroll
                for (int nt = 0; nt < NT; nt++) {
                    int nr = n0w + nt * 8 + g;
                    bh[nt][0] = *(const uint32_t*)&Bh[nr][kb + 2 * t];
                    bh[nt][1] = *(const uint32_t*)&Bh[nr][kb + 2 * t + 8];
                    bl[nt][0] = *(const uint32_t*)&Bl[nr][kb + 2 * t];
                    bl[nt][1] = *(const uint32_t*)&Bl[nr][kb + 2 * t + 8];
                }
#pragma unroll
                for (int mt = 0; mt < MT; mt++) {
                    int mr = m0w + mt * 16 + g;
                    uint32_t ah[4], al[4];
                    ah[0] = *(const uint32_t*)&Ah[mr][kb + 2 * t];
                    ah[1] = *(const uint32_t*)&Ah[mr + 8][kb + 2 * t];
                    ah[2] = *(const uint32_t*)&Ah[mr][kb + 2 * t + 8];
                    ah[3] = *(const uint32_t*)&Ah[mr + 8][kb + 2 * t + 8];
                    al[0] = *(const uint32_t*)&Al[mr][kb + 2 * t];
                    al[1] = *(const uint32_t*)&Al[mr + 8][kb + 2 * t];
                    al[2] = *(const uint32_t*)&Al[mr][kb + 2 * t + 8];
                    al[3] = *(const uint32_t*)&Al[mr + 8][kb + 2 * t + 8];
#pragma unroll
                    for (int nt = 0; nt < NT; nt++) {
                        mma16816(c[mt][nt], ah, bh[nt]);
                        mma16816(c[mt][nt], ah, bl[nt]);
                        mma16816(c[mt][nt], al, bh[nt]);
                    }
                }
            }
            __syncthreads();
        }
    }

    // ---- epilogue ----
#pragma unroll
    for (int mt = 0; mt < MT; mt++) {
#pragma unroll
        for (int half = 0; half < 2; half++) {
            int rloc = m0w + mt * 16 + g + half * 8;
            int row = m0 + rloc;
            float ps = 0.f, pd = 0.f;
#pragma unroll
            for (int nt = 0; nt < NT; nt++) {
                int col = n0w + nt * 8 + 2 * t;
                float vx = c[mt][nt][half * 2 + 0];
                float vy = c[mt][nt][half * 2 + 1];
                if (ALPHA) {
                    ps += vx * s_avs[col] + vy * s_avs[col + 1];
                    pd += vx * s_avd[col] + vy * s_avd[col + 1];
                }
                if (BIAS) {
                    float2 b2 = *(const float2*)(bias + col);
                    vx += b2.x; vy += b2.y;
                }
                if (RELU) { vx = fmaxf(vx, 0.f); vy = fmaxf(vy, 0.f); }
                if (row < NN) {
                    if (OSPLIT) {
                        bf162 hi, lo;
                        split2(vx, vy, hi, lo);
                        *(bf162*)&Ch[(size_t)row * BN + col] = hi;
                        *(bf162*)&Cl[(size_t)row * BN + col] = lo;
                    } else {
                        *(float2*)(C + (size_t)row * BN + col) = make_float2(vx, vy);
                    }
                }
            }
            if (ALPHA) {
                ps += __shfl_xor_sync(0xffffffffu, ps, 1);
                ps += __shfl_xor_sync(0xffffffffu, ps, 2);
                pd += __shfl_xor_sync(0xffffffffu, pd, 1);
                pd += __shfl_xor_sync(0xffffffffu, pd, 2);
                if (t == 0) {
                    atomicAdd(&s_as[rloc], ps);
                    atomicAdd(&s_ad[rloc], pd);
                }
            }
        }
    }
    if (ALPHA) {
        __syncthreads();
        if (tid < BM) {
            int row = m0 + tid;
            if (row < NN) { g_as[row] = s_as[tid]; g_ad[row] = s_ad[tid]; }
        }
    }
}

// ---------------- CSR gather kernels (warp per node, unroll-4) ----------------
// GCN layer 1 -> split only
__global__ void k_gcn_gather(const float* __restrict__ t,
                             bf16* __restrict__ oh, bf16* __restrict__ ol,
                             const float* __restrict__ bias) {
    int w = (blockIdx.x * blockDim.x + threadIdx.x) >> 5;
    int lane = threadIdx.x & 31;
    if (w >= NN) return;
    float di = g_dinv[w];
    int start = g_rowptr[w], end = g_rowptr[w + 1];
    float4 a0 = *(const float4*)(t + (size_t)w * DD + lane * 4);
    float cs = di * di;
    a0.x *= cs; a0.y *= cs; a0.z *= cs; a0.w *= cs;
    float4 a1 = make_float4(0.f, 0.f, 0.f, 0.f);
    float4 a2 = make_float4(0.f, 0.f, 0.f, 0.f);
    float4 a3 = make_float4(0.f, 0.f, 0.f, 0.f);
    int j = start;
    for (; j + 4 <= end; j += 4) {
        int s0 = g_csr[j], s1 = g_csr[j + 1], s2 = g_csr[j + 2], s3 = g_csr[j + 3];
        float c0 = g_dinv[s0] * di, c1 = g_dinv[s1] * di;
        float c2 = g_dinv[s2] * di, c3 = g_dinv[s3] * di;
        float4 v0 = *(const float4*)(t + (size_t)s0 * DD + lane * 4);
        float4 v1 = *(const float4*)(t + (size_t)s1 * DD + lane * 4);
        float4 v2 = *(const float4*)(t + (size_t)s2 * DD + lane * 4);
        float4 v3 = *(const float4*)(t + (size_t)s3 * DD + lane * 4);
        a0.x = fmaf(c0, v0.x, a0.x); a0.y = fmaf(c0, v0.y, a0.y);
        a0.z = fmaf(c0, v0.z, a0.z); a0.w = fmaf(c0, v0.w, a0.w);
        a1.x = fmaf(c1, v1.x, a1.x); a1.y = fmaf(c1, v1.y, a1.y);
        a1.z = fmaf(c1, v1.z, a1.z); a1.w = fmaf(c1, v1.w, a1.w);
        a2.x = fmaf(c2, v2.x, a2.x); a2.y = fmaf(c2, v2.y, a2.y);
        a2.z = fmaf(c2, v2.z, a2.z); a2.w = fmaf(c2, v2.w, a2.w);
        a3.x = fmaf(c3, v3.x, a3.x); a3.y = fmaf(c3, v3.y, a3.y);
        a3.z = fmaf(c3, v3.z, a3.z); a3.w = fmaf(c3, v3.w, a3.w);
    }
    for (; j < end; j++) {
        int s = g_csr[j];
        float cc = g_dinv[s] * di;
        float4 v = *(const float4*)(t + (size_t)s * DD + lane * 4);
        a0.x = fmaf(cc, v.x, a0.x); a0.y = fmaf(cc, v.y, a0.y);
        a0.z = fmaf(cc, v.z, a0.z); a0.w = fmaf(cc, v.w, a0.w);
    }
    a0.x += a1.x + a2.x + a3.x; a0.y += a1.y + a2.y + a3.y;
    a0.z += a1.z + a2.z + a3.z; a0.w += a1.w + a2.w + a3.w;
    float4 b = ((const float4*)bias)[lane];
    a0.x = fmaxf(a0.x + b.x, 0.f); a0.y = fmaxf(a0.y + b.y, 0.f);
    a0.z = fmaxf(a0.z + b.z, 0.f); a0.w = fmaxf(a0.w + b.w, 0.f);
    st_split4(oh, ol, (size_t)w * DD + lane * 4, a0);
}

// SAGE mean; reads split h1, writes split
__global__ void k_sage_mean(const bf16* __restrict__ hh, const bf16* __restrict__ hl,
                            bf16* __restrict__ oh, bf16* __restrict__ ol) {
    int w = (blockIdx.x * blockDim.x + threadIdx.x) >> 5;
    int lane = threadIdx.x & 31;
    if (w >= NN) return;
    int start = g_rowptr[w], end = g_rowptr[w + 1];
    float4 a0 = make_float4(0.f, 0.f, 0.f, 0.f);
    float4 a1 = make_float4(0.f, 0.f, 0.f, 0.f);
    int j = start;
    for (; j + 2 <= end; j += 2) {
        int s0 = g_csr[j], s1 = g_csr[j + 1];
        float4 v0 = ld_split4(hh, hl, (size_t)s0 * DD + lane * 4);
        float4 v1 = ld_split4(hh, hl, (size_t)s1 * DD + lane * 4);
        a0.x += v0.x; a0.y += v0.y; a0.z += v0.z; a0.w += v0.w;
        a1.x += v1.x; a1.y += v1.y; a1.z += v1.z; a1.w += v1.w;
    }
    if (j < end) {
        int s = g_csr[j];
        float4 v = ld_split4(hh, hl, (size_t)s * DD + lane * 4);
        a0.x += v.x; a0.y += v.y; a0.z += v.z; a0.w += v.w;
    }
    float cc = g_sinv[w];
    a0.x = (a0.x + a1.x) * cc; a0.y = (a0.y + a1.y) * cc;
    a0.z = (a0.z + a1.z) * cc; a0.w = (a0.w + a1.w) * cc;
    st_split4(oh, ol, (size_t)w * DD + lane * 4, a0);
}

// GAT -> split only (reads fp32 h and g_as/g_ad from fused GEMM epilogue)
__global__ void k_gat(const float* __restrict__ h,
                      bf16* __restrict__ oh, bf16* __restrict__ ol,
                      const float* __restrict__ bias) {
    int w = (blockIdx.x * blockDim.x + threadIdx.x) >> 5;
    int lane = threadIdx.x & 31;
    if (w >= NN) return;
    float ad_d = g_ad[w];
    float as_d = g_as[w];
    int start = g_rowptr[w], end = g_rowptr[w + 1];

    const float NEG = -1e30f;
    float m_l = NEG, s_l = 0.f;
    for (int j = start + lane; j < end; j += 32) {
        int s = g_csr[j];
        float e = leaky(g_as[s] + ad_d);
        if (e > m_l) { s_l *= __expf(m_l - e); m_l = e; }
        s_l += __expf(e - m_l);
    }
#pragma unroll
    for (int off = 16; off > 0; off >>= 1) {
        float m_o = __shfl_xor_sync(0xffffffffu, m_l, off);
        float s_o = __shfl_xor_sync(0xffffffffu, s_l, off);
        float m_n = fmaxf(m_l, m_o);
        s_l = s_l * __expf(m_l - m_n) + s_o * __expf(m_o - m_n);
        m_l = m_n;
    }
    float e_self = leaky(as_d + ad_d);
    float m = fmaxf(m_l, e_self);
    float den = s_l * __expf(m_l - m) + __expf(e_self - m);
    float inv_den = 1.0f / den;

    float wself = __expf(e_self - m) * inv_den;
    float4 a0 = *(const float4*)(h + (size_t)w * DD + lane * 4);
    a0.x *= wself; a0.y *= wself; a0.z *= wself; a0.w *= wself;
    float4 a1 = make_float4(0.f, 0.f, 0.f, 0.f);
    int j = start;
    for (; j + 2 <= end; j += 2) {
        int s0 = g_csr[j], s1 = g_csr[j + 1];
        float w0 = __expf(leaky(g_as[s0] + ad_d) - m) * inv_den;
        float w1 = __expf(leaky(g_as[s1] + ad_d) - m) * inv_den;
        float4 v0 = *(const float4*)(h + (size_t)s0 * DD + lane * 4);
        float4 v1 = *(const float4*)(h + (size_t)s1 * DD + lane * 4);
        a0.x = fmaf(w0, v0.x, a0.x); a0.y = fmaf(w0, v0.y, a0.y);
        a0.z = fmaf(w0, v0.z, a0.z); a0.w = fmaf(w0, v0.w, a0.w);
        a1.x = fmaf(w1, v1.x, a1.x); a1.y = fmaf(w1, v1.y, a1.y);
        a1.z = fmaf(w1, v1.z, a1.z); a1.w = fmaf(w1, v1.w, a1.w);
    }
    if (j < end) {
        int s = g_csr[j];
        float wgt = __expf(leaky(g_as[s] + ad_d) - m) * inv_den;
        float4 v = *(const float4*)(h + (size_t)s * DD + lane * 4);
        a0.x = fmaf(wgt, v.x, a0.x); a0.y = fmaf(wgt, v.y, a0.y);
        a0.z = fmaf(wgt, v.z, a0.z); a0.w = fmaf(wgt, v.w, a0.w);
    }
    a0.x += a1.x; a0.y += a1.y; a0.z += a1.z; a0.w += a1.w;
    float4 b = ((const float4*)bias)[lane];
    a0.x = fmaxf(a0.x + b.x, 0.f); a0.y = fmaxf(a0.y + b.y, 0.f);
    a0.z = fmaxf(a0.z + b.z, 0.f); a0.w = fmaxf(a0.w + b.w, 0.f);
    st_split4(oh, ol, (size_t)w * DD + lane * 4, a0);
}

__global__ void k_out_gather(const float* __restrict__ t, float* __restrict__ out,
                             const float* __restrict__ bias) {
    int w = (blockIdx.x * blockDim.x + threadIdx.x) >> 5;
    int lane = threadIdx.x & 31;
    if (w >= NN) return;
    float di = g_dinv[w];
    int start = g_rowptr[w], end = g_rowptr[w + 1];
    float2 a0 = *(const float2*)(t + (size_t)w * OO + lane * 2);
    float cs = di * di;
    a0.x *= cs; a0.y *= cs;
    float2 a1 = make_float2(0.f, 0.f);
    float2 a2 = make_float2(0.f, 0.f);
    float2 a3 = make_float2(0.f, 0.f);
    int j = start;
    for (; j + 4 <= end; j += 4) {
        int s0 = g_csr[j], s1 = g_csr[j + 1], s2 = g_csr[j + 2], s3 = g_csr[j + 3];
        float c0 = g_dinv[s0] * di, c1 = g_dinv[s1] * di;
        float c2 = g_dinv[s2] * di, c3 = g_dinv[s3] * di;
        float2 v0 = *(const float2*)(t + (size_t)s0 * OO + lane * 2);
        float2 v1 = *(const float2*)(t + (size_t)s1 * OO + lane * 2);
        float2 v2 = *(const float2*)(t + (size_t)s2 * OO + lane * 2);
        float2 v3 = *(const float2*)(t + (size_t)s3 * OO + lane * 2);
        a0.x = fmaf(c0, v0.x, a0.x); a0.y = fmaf(c0, v0.y, a0.y);
        a1.x = fmaf(c1, v1.x, a1.x); a1.y = fmaf(c1, v1.y, a1.y);
        a2.x = fmaf(c2, v2.x, a2.x); a2.y = fmaf(c2, v2.y, a2.y);
        a3.x = fmaf(c3, v3.x, a3.x); a3.y = fmaf(c3, v3.y, a3.y);
    }
    for (; j < end; j++) {
        int s = g_csr[j];
        float cc = g_dinv[s] * di;
        float2 v = *(const float2*)(t + (size_t)s * OO + lane * 2);
        a0.x = fmaf(cc, v.x, a0.x); a0.y = fmaf(cc, v.y, a0.y);
    }
    float2 b = ((const float2*)bias)[lane];
    a0.x += a1.x + a2.x + a3.x + b.x;
    a0.y += a1.y + a2.y + a3.y + b.y;
    *(float2*)(out + (size_t)w * OO + lane * 2) = a0;
}

// ---------------- launch ----------------
extern "C" void kernel_launch(void* const* d_in, const int* in_sizes, int n_in,
                              void* d_out, int out_size) {
    const float* x  = (const float*)d_in[0];
    const void*  ei = d_in[1];
    const float* W1 = (const float*)d_in[2];
    const float* b1 = (const float*)d_in[3];
    const float* Wl = (const float*)d_in[4];
    const float* Wr = (const float*)d_in[5];
    const float* bs = (const float*)d_in[6];
    const float* Wg = (const float*)d_in[7];
    const float* a_s = (const float*)d_in[8];
    const float* a_d = (const float*)d_in[9];
    const float* bg = (const float*)d_in[10];
    const float* Wo = (const float*)d_in[11];
    const float* bo = (const float*)d_in[12];
    float* out = (float*)d_out;

    float *p_t, *p_agg;
    bf16 *p0h, *p0l, *p1h, *p1l, *p2h, *p2l, *pwh, *pwl;
    cudaGetSymbolAddress((void**)&p_t, g_t);
    cudaGetSymbolAddress((void**)&p_agg, g_agg);
    cudaGetSymbolAddress((void**)&p0h, g_p0h);
    cudaGetSymbolAddress((void**)&p0l, g_p0l);
    cudaGetSymbolAddress((void**)&p1h, g_p1h);
    cudaGetSymbolAddress((void**)&p1l, g_p1l);
    cudaGetSymbolAddress((void**)&p2h, g_p2h);
    cudaGetSymbolAddress((void**)&p2l, g_p2l);
    cudaGetSymbolAddress((void**)&pwh, g_wh);
    cudaGetSymbolAddress((void**)&pwl, g_wl);

    const int TB = 256;
    const int bN   = (NN + TB - 1) / TB;
    const int bE   = NE / TB;
    const int bNW  = (NN * 32 + TB - 1) / TB;
    const int bPrep = (WTOT + NN * DD / 4 + TB - 1) / TB;
    const int gGemm = (NN + 127) / 128;

    // setup: detect+zero, degrees, scan+scales, CSR fill, weight/x split
    k_detect_zero<<<bN, TB>>>((const long long*)ei);
    k_deg<<<bE, TB>>>(ei);
    k_scan_scal<<<1, 1024>>>();
    k_fill<<<bE, TB>>>(ei);
    k_prep<<<bPrep, TB>>>(W1, Wl, Wr, Wg, Wo, x, pwh, pwl, p0h, p0l);

    // ---- layer 1: GCN + relu ----
    k_gemm_bf<128, false, false, false, false, false><<<gGemm, TB>>>(
        p0h, p0l, nullptr, nullptr, pwh + WOFF_W1, pwl + WOFF_W1, nullptr, nullptr,
        p_t, nullptr, nullptr, nullptr, nullptr, nullptr);
    k_gcn_gather<<<bNW, TB>>>(p_t, p1h, p1l, b1);        // h1 split in P1

    // ---- layer 2: SAGE(mean) + relu ----
    k_sage_mean<<<bNW, TB>>>(p1h, p1l, p2h, p2l);        // agg split in P2
    k_gemm_bf<128, true, true, true, true, false><<<gGemm, TB>>>(
        p2h, p2l, p1h, p1l, pwh + WOFF_WL, pwl + WOFF_WL, pwh + WOFF_WR, pwl + WOFF_WR,
        nullptr, p0h, p0l, bs, nullptr, nullptr);        // h2 split in P0

    // ---- layer 3: GAT + relu (alpha fused into GEMM epilogue) ----
    k_gemm_bf<128, false, false, false, false, true><<<gGemm, TB>>>(
        p0h, p0l, nullptr, nullptr, pwh + WOFF_WG, pwl + WOFF_WG, nullptr, nullptr,
        p_agg, nullptr, nullptr, nullptr, a_s, a_d);     // g fp32 + g_as/g_ad
    k_gat<<<bNW, TB>>>(p_agg, p1h, p1l, bg);             // h3 split in P1

    // ---- layer 4: GCN output ----
    k_gemm_bf<64, false, false, false, false, false><<<gGemm, TB>>>(
        p1h, p1l, nullptr, nullptr, pwh + WOFF_WO, pwl + WOFF_WO, nullptr, nullptr,
        p_t, nullptr, nullptr, nullptr, nullptr, nullptr);
    k_out_gather<<<bNW, TB>>>(p_t, out, bo);
}

// round 9
// speedup vs baseline: 1.0231x; 1.0231x over previous
#include <cuda_runtime.h>
#include <cuda_bf16.h>
#include <math.h>
#include <stdint.h>

#define NN 50000
#define NE 1600000
#define DD 128
#define OO 64

typedef __nv_bfloat16 bf16;
typedef __nv_bfloat162 bf162;

// ---------------- device scratch ----------------
__device__ int   g_is64;
__device__ int   g_deg[NN];
__device__ float g_dinv[NN];
__device__ float g_sinv[NN];
__device__ float g_as[NN];
__device__ float g_ad[NN];
__device__ int   g_rowptr[NN + 1];
__device__ int   g_cur[NN];
__device__ int   g_csr[NE];
__device__ float g_t[(size_t)NN * DD];
__device__ float g_agg[(size_t)NN * DD];
// packed split-bf16 feature buffers: 16B group = [hi0..hi3, lo0..lo3] per 4 values
__device__ bf16  g_p0[(size_t)NN * DD * 2];
__device__ bf16  g_p1[(size_t)NN * DD * 2];
__device__ bf16  g_p2[(size_t)NN * DD * 2];
// packed split weights, transposed to [n][k], k=128. Element offsets (x2 for packed).
#define WOFF_W1 0
#define WOFF_WL 16384
#define WOFF_WR 32768
#define WOFF_WG 49152
#define WOFF_WO 65536
#define WTOT    73728
__device__ bf16  g_w[(size_t)WTOT * 2];

__device__ __forceinline__ float leaky(float v) { return v > 0.f ? v : 0.2f * v; }

__device__ __forceinline__ void split2(float x, float y, bf162& hi, bf162& lo) {
    hi = __float22bfloat162_rn(make_float2(x, y));
    lo = __float22bfloat162_rn(make_float2(x - __bfloat162float(hi.x),
                                           y - __bfloat162float(hi.y)));
}

// store 4 fp32 values as one 16B packed group. elem_base multiple of 4.
__device__ __forceinline__ void st_packed4(bf16* p, size_t elem_base, float4 v) {
    bf162 h0, l0, h1, l1;
    split2(v.x, v.y, h0, l0);
    split2(v.z, v.w, h1, l1);
    uint4 u;
    u.x = *(uint32_t*)&h0; u.y = *(uint32_t*)&h1;
    u.z = *(uint32_t*)&l0; u.w = *(uint32_t*)&l1;
    *(uint4*)&p[elem_base * 2] = u;
}

// load 4 fp32 values from one 16B packed group
__device__ __forceinline__ float4 ld_packed4(const bf16* __restrict__ p, size_t elem_base) {
    uint4 u = *(const uint4*)&p[elem_base * 2];
    bf162 h0 = *(bf162*)&u.x, h1 = *(bf162*)&u.y;
    bf162 l0 = *(bf162*)&u.z, l1 = *(bf162*)&u.w;
    float4 r;
    r.x = __bfloat162float(h0.x) + __bfloat162float(l0.x);
    r.y = __bfloat162float(h0.y) + __bfloat162float(l0.y);
    r.z = __bfloat162float(h1.x) + __bfloat162float(l1.x);
    r.w = __bfloat162float(h1.y) + __bfloat162float(l1.y);
    return r;
}

__device__ __forceinline__ void edge_ld(const void* ei, int e, int& s, int& d) {
    if (g_is64) {
        const long long* p = (const long long*)ei;
        s = (int)p[e]; d = (int)p[NE + e];
    } else {
        const int* p = (const int*)ei;
        s = p[e]; d = p[NE + e];
    }
}

// ---------------- setup ----------------
__global__ void k_detect_zero(const long long* ei) {
    int i = blockIdx.x * blockDim.x + threadIdx.x;
    if (i == 0) {
        bool is64 = true;
        for (int q = 0; q < 64; q++) {
            long long v = ei[q];
            if (v < 0 || v >= NN) { is64 = false; break; }
        }
        g_is64 = is64 ? 1 : 0;
    }
    if (i < NN) g_deg[i] = 0;
}

// degree pass: read ONLY the dst half of the edge list
__global__ void k_deg(const void* ei) {
    int e = blockIdx.x * blockDim.x + threadIdx.x;
    if (e >= NE) return;
    int d;
    if (g_is64) d = (int)((const long long*)ei)[NE + e];
    else        d = ((const int*)ei)[NE + e];
    atomicAdd(&g_deg[d], 1);
}

// scan + per-node scale factors, single block
__global__ void __launch_bounds__(1024) k_scan_scal() {
    __shared__ int sh[1024];
    __shared__ int sh_carry;
    int tid = threadIdx.x;
    if (tid == 0) { sh_carry = 0; g_rowptr[0] = 0; }
    __syncthreads();
    for (int base = 0; base < NN; base += 1024) {
        int i = base + tid;
        int v = (i < NN) ? g_deg[i] : 0;
        sh[tid] = v;
        __syncthreads();
#pragma unroll
        for (int off = 1; off < 1024; off <<= 1) {
            int t = (tid >= off) ? sh[tid - off] : 0;
            __syncthreads();
            sh[tid] += t;
            __syncthreads();
        }
        int carry = sh_carry;
        if (i < NN) {
            int excl = carry + sh[tid] - v;
            g_rowptr[i + 1] = carry + sh[tid];
            g_cur[i] = excl;
            g_dinv[i] = rsqrtf((float)(v + 1));
            g_sinv[i] = 1.0f / (float)max(v, 1);
        }
        __syncthreads();
        if (tid == 0) sh_carry = carry + sh[1023];
        __syncthreads();
    }
}

__global__ void k_fill(const void* ei) {
    int e = blockIdx.x * blockDim.x + threadIdx.x;
    if (e >= NE) return;
    int s, d; edge_ld(ei, e, s, d);
    int pos = atomicAdd(&g_cur[d], 1);
    g_csr[pos] = s;
}

// ---------------- merged one-shot prep: pack 5 weights (transposed) + x ----------------
__global__ void k_prep(const float* __restrict__ W1, const float* __restrict__ Wl,
                       const float* __restrict__ Wr, const float* __restrict__ Wg,
                       const float* __restrict__ Wo, const float* __restrict__ x,
                       bf16* __restrict__ w, bf16* __restrict__ xp) {
    int i = blockIdx.x * blockDim.x + threadIdx.x;
    if (i < WTOT) {
        const float* src; int N, off, li;
        if (i < 65536) {
            int wi = i >> 14; li = i & 16383; off = wi << 14; N = 128;
            src = (wi == 0) ? W1 : (wi == 1) ? Wl : (wi == 2) ? Wr : Wg;
        } else {
            li = i - 65536; off = 65536; N = 64; src = Wo;
        }
        int k = li / N, n = li % N;
        float v = src[li];
        bf16 hi = __float2bfloat16_rn(v);
        size_t base = (size_t)off * 2 + (size_t)n * 256 + (k >> 2) * 8 + (k & 3);
        w[base]     = hi;
        w[base + 4] = __float2bfloat16_rn(v - __bfloat162float(hi));
    } else {
        int j = i - WTOT;                       // float4 group index into x
        if (j < NN * DD / 4) {
            float4 v = ((const float4*)x)[j];
            st_packed4(xp, (size_t)j * 4, v);
        }
    }
}

// ---------------- tensor-core GEMM on packed split bf16 ----------------
__device__ __forceinline__ void mma16816(float* c, const uint32_t* a, const uint32_t* b) {
    asm volatile(
        "mma.sync.aligned.m16n8k16.row.col.f32.bf16.bf16.f32 "
        "{%0,%1,%2,%3}, {%4,%5,%6,%7}, {%8,%9}, {%0,%1,%2,%3};"
        : "+f"(c[0]), "+f"(c[1]), "+f"(c[2]), "+f"(c[3])
        : "r"(a[0]), "r"(a[1]), "r"(a[2]), "r"(a[3]), "r"(b[0]), "r"(b[1]));
}

// C[NN x BN] = A@B^T (+A2@B2) (+bias)(relu). A,B packed split. OSPLIT: packed out.
// ALPHA: per-row dots with a_s/a_d into g_as/g_ad (BN==128 only).
template<int BN, bool TWO, bool BIAS, bool RELU, bool OSPLIT, bool ALPHA>
__global__ void __launch_bounds__(256) k_gemm_bf(
        const bf16* __restrict__ A1p, const bf16* __restrict__ A2p,
        const bf16* __restrict__ B1p, const bf16* __restrict__ B2p,
        float* __restrict__ C, bf16* __restrict__ Cp,
        const float* __restrict__ bias,
        const float* __restrict__ avs, const float* __restrict__ avd) {
    constexpr int BM = 128, BK = 32, LD = 40;
    constexpr int MWARPS = (BN == 128) ? 2 : 4;
    constexpr int MW = BM / MWARPS;
    constexpr int MT = MW / 16;
    constexpr int NT = 4;

    __shared__ bf16 Ah[BM][LD];
    __shared__ bf16 Al[BM][LD];
    __shared__ bf16 Bh[BN][LD];
    __shared__ bf16 Bl[BN][LD];
    __shared__ float s_as[ALPHA ? BM : 1];
    __shared__ float s_ad[ALPHA ? BM : 1];
    __shared__ float s_avs[ALPHA ? BN : 1];
    __shared__ float s_avd[ALPHA ? BN : 1];

    const int tid = threadIdx.x;
    const int wid = tid >> 5;
    const int lane = tid & 31;
    const int g = lane >> 2;
    const int t = lane & 3;
    const int wm = wid % MWARPS;
    const int wn = wid / MWARPS;
    const int m0 = blockIdx.x * BM;
    const int m0w = wm * MW;
    const int n0w = wn * 32;

    if (ALPHA && tid < BM) {
        s_as[tid] = 0.f; s_ad[tid] = 0.f;
        s_avs[tid] = avs[tid]; s_avd[tid] = avd[tid];
    }

    float c[MT][NT][4];
#pragma unroll
    for (int i = 0; i < MT; i++)
#pragma unroll
        for (int j = 0; j < NT; j++)
#pragma unroll
            for (int q = 0; q < 4; q++) c[i][j][q] = 0.f;

    const int NPH = TWO ? 2 : 1;
    for (int ph = 0; ph < NPH; ph++) {
        const bf16* Ap = (TWO && ph) ? A2p : A1p;
        const bf16* Bp = (TWO && ph) ? B2p : B1p;
#pragma unroll
        for (int k0 = 0; k0 < DD; k0 += BK) {
            // A tile: each thread covers 8 elems = 2 packed groups = 32B contiguous
#pragma unroll
            for (int l = 0; l < 2; l++) {
                int idx = tid + l * 256;
                int m = idx >> 2;
                int ko = (idx & 3) * 8;
                int gr = m0 + m;
                uint4 v0 = make_uint4(0, 0, 0, 0), v1 = make_uint4(0, 0, 0, 0);
                if (gr < NN) {
                    const uint4* p = (const uint4*)&Ap[(size_t)gr * 256 + (k0 + ko) * 2];
                    v0 = p[0]; v1 = p[1];
                }
                *(uint4*)&Ah[m][ko] = make_uint4(v0.x, v0.y, v1.x, v1.y);
                *(uint4*)&Al[m][ko] = make_uint4(v0.z, v0.w, v1.z, v1.w);
            }
            constexpr int NB = (BN * BK) / (8 * 256);
#pragma unroll
            for (int l = 0; l < NB; l++) {
                int idx = tid + l * 256;
                int n = idx >> 2;
                int ko = (idx & 3) * 8;
                const uint4* p = (const uint4*)&Bp[(size_t)n * 256 + (k0 + ko) * 2];
                uint4 v0 = p[0], v1 = p[1];
                *(uint4*)&Bh[n][ko] = make_uint4(v0.x, v0.y, v1.x, v1.y);
                *(uint4*)&Bl[n][ko] = make_uint4(v0.z, v0.w, v1.z, v1.w);
            }
            __syncthreads();
#pragma unroll
            for (int s = 0; s < 2; s++) {
                const int kb = s * 16;
                uint32_t bh[NT][2], bl[NT][2];
#pragma unroll
                for (int nt = 0; nt < NT; nt++) {
                    int nr = n0w + nt * 8 + g;
                    bh[nt][0] = *(const uint32_t*)&Bh[nr][kb + 2 * t];
                    bh[nt][1] = *(const uint32_t*)&Bh[nr][kb + 2 * t + 8];
                    bl[nt][0] = *(const uint32_t*)&Bl[nr][kb + 2 * t];
                    bl[nt][1] = *(const uint32_t*)&Bl[nr][kb + 2 * t + 8];
                }
#pragma unroll
                for (int mt = 0; mt < MT; mt++) {
                    int mr = m0w + mt * 16 + g;
                    uint32_t ah[4], al[4];
                    ah[0] = *(const uint32_t*)&Ah[mr][kb + 2 * t];
                    ah[1] = *(const uint32_t*)&Ah[mr + 8][kb + 2 * t];
                    ah[2] = *(const uint32_t*)&Ah[mr][kb + 2 * t + 8];
                    ah[3] = *(const uint32_t*)&Ah[mr + 8][kb + 2 * t + 8];
                    al[0] = *(const uint32_t*)&Al[mr][kb + 2 * t];
                    al[1] = *(const uint32_t*)&Al[mr + 8][kb + 2 * t];
                    al[2] = *(const uint32_t*)&Al[mr][kb + 2 * t + 8];
                    al[3] = *(const uint32_t*)&Al[mr + 8][kb + 2 * t + 8];
#pragma unroll
                    for (int nt = 0; nt < NT; nt++) {
                        mma16816(c[mt][nt], ah, bh[nt]);
                        mma16816(c[mt][nt], ah, bl[nt]);
                        mma16816(c[mt][nt], al, bh[nt]);
                    }
                }
            }
            __syncthreads();
        }
    }

    // ---- epilogue ----
#pragma unroll
    for (int mt = 0; mt < MT; mt++) {
#pragma unroll
        for (int half = 0; half < 2; half++) {
            int rloc = m0w + mt * 16 + g + half * 8;
            int row = m0 + rloc;
            float ps = 0.f, pd = 0.f;
#pragma unroll
            for (int nt = 0; nt < NT; nt++) {
                int col = n0w + nt * 8 + 2 * t;
                float vx = c[mt][nt][half * 2 + 0];
                float vy = c[mt][nt][half * 2 + 1];
                if (ALPHA) {
                    ps += vx * s_avs[col] + vy * s_avs[col + 1];
                    pd += vx * s_avd[col] + vy * s_avd[col + 1];
                }
                if (BIAS) {
                    float2 b2 = *(const float2*)(bias + col);
                    vx += b2.x; vy += b2.y;
                }
                if (RELU) { vx = fmaxf(vx, 0.f); vy = fmaxf(vy, 0.f); }
                if (row < NN) {
                    if (OSPLIT) {
                        bf162 hi, lo;
                        split2(vx, vy, hi, lo);
                        size_t gb = (size_t)row * BN * 2 + (col >> 2) * 8 + (col & 3);
                        *(bf162*)&Cp[gb]     = hi;
                        *(bf162*)&Cp[gb + 4] = lo;
                    } else {
                        *(float2*)(C + (size_t)row * BN + col) = make_float2(vx, vy);
                    }
                }
            }
            if (ALPHA) {
                ps += __shfl_xor_sync(0xffffffffu, ps, 1);
                ps += __shfl_xor_sync(0xffffffffu, ps, 2);
                pd += __shfl_xor_sync(0xffffffffu, pd, 1);
                pd += __shfl_xor_sync(0xffffffffu, pd, 2);
                if (t == 0) {
                    atomicAdd(&s_as[rloc], ps);
                    atomicAdd(&s_ad[rloc], pd);
                }
            }
        }
    }
    if (ALPHA) {
        __syncthreads();
        if (tid < BM) {
            int row = m0 + tid;
            if (row < NN) { g_as[row] = s_as[tid]; g_ad[row] = s_ad[tid]; }
        }
    }
}

// ---------------- CSR gather kernels (warp per node) ----------------
// GCN layer 1: reads fp32 t, writes packed split h1 (one 16B store)
__global__ void k_gcn_gather(const float* __restrict__ t, bf16* __restrict__ op,
                             const float* __restrict__ bias) {
    int w = (blockIdx.x * blockDim.x + threadIdx.x) >> 5;
    int lane = threadIdx.x & 31;
    if (w >= NN) return;
    float di = g_dinv[w];
    int start = g_rowptr[w], end = g_rowptr[w + 1];
    float4 a0 = *(const float4*)(t + (size_t)w * DD + lane * 4);
    float cs = di * di;
    a0.x *= cs; a0.y *= cs; a0.z *= cs; a0.w *= cs;
    float4 a1 = make_float4(0.f, 0.f, 0.f, 0.f);
    float4 a2 = make_float4(0.f, 0.f, 0.f, 0.f);
    float4 a3 = make_float4(0.f, 0.f, 0.f, 0.f);
    int j = start;
    for (; j + 4 <= end; j += 4) {
        int s0 = g_csr[j], s1 = g_csr[j + 1], s2 = g_csr[j + 2], s3 = g_csr[j + 3];
        float c0 = g_dinv[s0] * di, c1 = g_dinv[s1] * di;
        float c2 = g_dinv[s2] * di, c3 = g_dinv[s3] * di;
        float4 v0 = *(const float4*)(t + (size_t)s0 * DD + lane * 4);
        float4 v1 = *(const float4*)(t + (size_t)s1 * DD + lane * 4);
        float4 v2 = *(const float4*)(t + (size_t)s2 * DD + lane * 4);
        float4 v3 = *(const float4*)(t + (size_t)s3 * DD + lane * 4);
        a0.x = fmaf(c0, v0.x, a0.x); a0.y = fmaf(c0, v0.y, a0.y);
        a0.z = fmaf(c0, v0.z, a0.z); a0.w = fmaf(c0, v0.w, a0.w);
        a1.x = fmaf(c1, v1.x, a1.x); a1.y = fmaf(c1, v1.y, a1.y);
        a1.z = fmaf(c1, v1.z, a1.z); a1.w = fmaf(c1, v1.w, a1.w);
        a2.x = fmaf(c2, v2.x, a2.x); a2.y = fmaf(c2, v2.y, a2.y);
        a2.z = fmaf(c2, v2.z, a2.z); a2.w = fmaf(c2, v2.w, a2.w);
        a3.x = fmaf(c3, v3.x, a3.x); a3.y = fmaf(c3, v3.y, a3.y);
        a3.z = fmaf(c3, v3.z, a3.z); a3.w = fmaf(c3, v3.w, a3.w);
    }
    for (; j < end; j++) {
        int s = g_csr[j];
        float cc = g_dinv[s] * di;
        float4 v = *(const float4*)(t + (size_t)s * DD + lane * 4);
        a0.x = fmaf(cc, v.x, a0.x); a0.y = fmaf(cc, v.y, a0.y);
        a0.z = fmaf(cc, v.z, a0.z); a0.w = fmaf(cc, v.w, a0.w);
    }
    a0.x += a1.x + a2.x + a3.x; a0.y += a1.y + a2.y + a3.y;
    a0.z += a1.z + a2.z + a3.z; a0.w += a1.w + a2.w + a3.w;
    float4 b = ((const float4*)bias)[lane];
    a0.x = fmaxf(a0.x + b.x, 0.f); a0.y = fmaxf(a0.y + b.y, 0.f);
    a0.z = fmaxf(a0.z + b.z, 0.f); a0.w = fmaxf(a0.w + b.w, 0.f);
    st_packed4(op, (size_t)w * DD + lane * 4, a0);
}

// SAGE mean: reads packed h1 (one 16B load per neighbor-chunk), writes packed
__global__ void k_sage_mean(const bf16* __restrict__ hp, bf16* __restrict__ op) {
    int w = (blockIdx.x * blockDim.x + threadIdx.x) >> 5;
    int lane = threadIdx.x & 31;
    if (w >= NN) return;
    int start = g_rowptr[w], end = g_rowptr[w + 1];
    float4 a0 = make_float4(0.f, 0.f, 0.f, 0.f);
    float4 a1 = make_float4(0.f, 0.f, 0.f, 0.f);
    int j = start;
    for (; j + 2 <= end; j += 2) {
        int s0 = g_csr[j], s1 = g_csr[j + 1];
        float4 v0 = ld_packed4(hp, (size_t)s0 * DD + lane * 4);
        float4 v1 = ld_packed4(hp, (size_t)s1 * DD + lane * 4);
        a0.x += v0.x; a0.y += v0.y; a0.z += v0.z; a0.w += v0.w;
        a1.x += v1.x; a1.y += v1.y; a1.z += v1.z; a1.w += v1.w;
    }
    if (j < end) {
        int s = g_csr[j];
        float4 v = ld_packed4(hp, (size_t)s * DD + lane * 4);
        a0.x += v.x; a0.y += v.y; a0.z += v.z; a0.w += v.w;
    }
    float cc = g_sinv[w];
    a0.x = (a0.x + a1.x) * cc; a0.y = (a0.y + a1.y) * cc;
    a0.z = (a0.z + a1.z) * cc; a0.w = (a0.w + a1.w) * cc;
    st_packed4(op, (size_t)w * DD + lane * 4, a0);
}

// GAT: reads fp32 h (g_agg) + g_as/g_ad from fused GEMM epilogue, writes packed
__global__ void k_gat(const float* __restrict__ h, bf16* __restrict__ op,
                      const float* __restrict__ bias) {
    int w = (blockIdx.x * blockDim.x + threadIdx.x) >> 5;
    int lane = threadIdx.x & 31;
    if (w >= NN) return;
    float ad_d = g_ad[w];
    float as_d = g_as[w];
    int start = g_rowptr[w], end = g_rowptr[w + 1];

    const float NEG = -1e30f;
    float m_l = NEG, s_l = 0.f;
    for (int j = start + lane; j < end; j += 32) {
        int s = g_csr[j];
        float e = leaky(g_as[s] + ad_d);
        if (e > m_l) { s_l *= __expf(m_l - e); m_l = e; }
        s_l += __expf(e - m_l);
    }
#pragma unroll
    for (int off = 16; off > 0; off >>= 1) {
        float m_o = __shfl_xor_sync(0xffffffffu, m_l, off);
        float s_o = __shfl_xor_sync(0xffffffffu, s_l, off);
        float m_n = fmaxf(m_l, m_o);
        s_l = s_l * __expf(m_l - m_n) + s_o * __expf(m_o - m_n);
        m_l = m_n;
    }
    float e_self = leaky(as_d + ad_d);
    float m = fmaxf(m_l, e_self);
    float den = s_l * __expf(m_l - m) + __expf(e_self - m);
    float inv_den = 1.0f / den;

    float wself = __expf(e_self - m) * inv_den;
    float4 a0 = *(const float4*)(h + (size_t)w * DD + lane * 4);
    a0.x *= wself; a0.y *= wself; a0.z *= wself; a0.w *= wself;
    float4 a1 = make_float4(0.f, 0.f, 0.f, 0.f);
    int j = start;
    for (; j + 2 <= end; j += 2) {
        int s0 = g_csr[j], s1 = g_csr[j + 1];
        float w0 = __expf(leaky(g_as[s0] + ad_d) - m) * inv_den;
        float w1 = __expf(leaky(g_as[s1] + ad_d) - m) * inv_den;
        float4 v0 = *(const float4*)(h + (size_t)s0 * DD + lane * 4);
        float4 v1 = *(const float4*)(h + (size_t)s1 * DD + lane * 4);
        a0.x = fmaf(w0, v0.x, a0.x); a0.y = fmaf(w0, v0.y, a0.y);
        a0.z = fmaf(w0, v0.z, a0.z); a0.w = fmaf(w0, v0.w, a0.w);
        a1.x = fmaf(w1, v1.x, a1.x); a1.y = fmaf(w1, v1.y, a1.y);
        a1.z = fmaf(w1, v1.z, a1.z); a1.w = fmaf(w1, v1.w, a1.w);
    }
    if (j < end) {
        int s = g_csr[j];
        float wgt = __expf(leaky(g_as[s] + ad_d) - m) * inv_den;
        float4 v = *(const float4*)(h + (size_t)s * DD + lane * 4);
        a0.x = fmaf(wgt, v.x, a0.x); a0.y = fmaf(wgt, v.y, a0.y);
        a0.z = fmaf(wgt, v.z, a0.z); a0.w = fmaf(wgt, v.w, a0.w);
    }
    a0.x += a1.x; a0.y += a1.y; a0.z += a1.z; a0.w += a1.w;
    float4 b = ((const float4*)bias)[lane];
    a0.x = fmaxf(a0.x + b.x, 0.f); a0.y = fmaxf(a0.y + b.y, 0.f);
    a0.z = fmaxf(a0.z + b.z, 0.f); a0.w = fmaxf(a0.w + b.w, 0.f);
    st_packed4(op, (size_t)w * DD + lane * 4, a0);
}

__global__ void k_out_gather(const float* __restrict__ t, float* __restrict__ out,
                             const float* __restrict__ bias) {
    int w = (blockIdx.x * blockDim.x + threadIdx.x) >> 5;
    int lane = threadIdx.x & 31;
    if (w >= NN) return;
    float di = g_dinv[w];
    int start = g_rowptr[w], end = g_rowptr[w + 1];
    float2 a0 = *(const float2*)(t + (size_t)w * OO + lane * 2);
    float cs = di * di;
    a0.x *= cs; a0.y *= cs;
    float2 a1 = make_float2(0.f, 0.f);
    float2 a2 = make_float2(0.f, 0.f);
    float2 a3 = make_float2(0.f, 0.f);
    int j = start;
    for (; j + 4 <= end; j += 4) {
        int s0 = g_csr[j], s1 = g_csr[j + 1], s2 = g_csr[j + 2], s3 = g_csr[j + 3];
        float c0 = g_dinv[s0] * di, c1 = g_dinv[s1] * di;
        float c2 = g_dinv[s2] * di, c3 = g_dinv[s3] * di;
        float2 v0 = *(const float2*)(t + (size_t)s0 * OO + lane * 2);
        float2 v1 = *(const float2*)(t + (size_t)s1 * OO + lane * 2);
        float2 v2 = *(const float2*)(t + (size_t)s2 * OO + lane * 2);
        float2 v3 = *(const float2*)(t + (size_t)s3 * OO + lane * 2);
        a0.x = fmaf(c0, v0.x, a0.x); a0.y = fmaf(c0, v0.y, a0.y);
        a1.x = fmaf(c1, v1.x, a1.x); a1.y = fmaf(c1, v1.y, a1.y);
        a2.x = fmaf(c2, v2.x, a2.x); a2.y = fmaf(c2, v2.y, a2.y);
        a3.x = fmaf(c3, v3.x, a3.x); a3.y = fmaf(c3, v3.y, a3.y);
    }
    for (; j < end; j++) {
        int s = g_csr[j];
        float cc = g_dinv[s] * di;
        float2 v = *(const float2*)(t + (size_t)s * OO + lane * 2);
        a0.x = fmaf(cc, v.x, a0.x); a0.y = fmaf(cc, v.y, a0.y);
    }
    float2 b = ((const float2*)bias)[lane];
    a0.x += a1.x + a2.x + a3.x + b.x;
    a0.y += a1.y + a2.y + a3.y + b.y;
    *(float2*)(out + (size_t)w * OO + lane * 2) = a0;
}

// ---------------- launch ----------------
extern "C" void kernel_launch(void* const* d_in, const int* in_sizes, int n_in,
                              void* d_out, int out_size) {
    const float* x  = (const float*)d_in[0];
    const void*  ei = d_in[1];
    const float* W1 = (const float*)d_in[2];
    const float* b1 = (const float*)d_in[3];
    const float* Wl = (const float*)d_in[4];
    const float* Wr = (const float*)d_in[5];
    const float* bs = (const float*)d_in[6];
    const float* Wg = (const float*)d_in[7];
    const float* a_s = (const float*)d_in[8];
    const float* a_d = (const float*)d_in[9];
    const float* bg = (const float*)d_in[10];
    const float* Wo = (const float*)d_in[11];
    const float* bo = (const float*)d_in[12];
    float* out = (float*)d_out;

    float *p_t, *p_agg;
    bf16 *p0, *p1, *p2, *pw;
    cudaGetSymbolAddress((void**)&p_t, g_t);
    cudaGetSymbolAddress((void**)&p_agg, g_agg);
    cudaGetSymbolAddress((void**)&p0, g_p0);
    cudaGetSymbolAddress((void**)&p1, g_p1);
    cudaGetSymbolAddress((void**)&p2, g_p2);
    cudaGetSymbolAddress((void**)&pw, g_w);

    const int TB = 256;
    const int bN   = (NN + TB - 1) / TB;
    const int bE   = NE / TB;
    const int bNW  = (NN * 32 + TB - 1) / TB;
    const int bPrep = (WTOT + NN * DD / 4 + TB - 1) / TB;
    const int gGemm = (NN + 127) / 128;

    // setup
    k_detect_zero<<<bN, TB>>>((const long long*)ei);
    k_deg<<<bE, TB>>>(ei);
    k_scan_scal<<<1, 1024>>>();
    k_fill<<<bE, TB>>>(ei);
    k_prep<<<bPrep, TB>>>(W1, Wl, Wr, Wg, Wo, x, pw, p0);

    // ---- layer 1: GCN + relu ----
    k_gemm_bf<128, false, false, false, false, false><<<gGemm, TB>>>(
        p0, nullptr, pw + 2 * WOFF_W1, nullptr,
        p_t, nullptr, nullptr, nullptr, nullptr);
    k_gcn_gather<<<bNW, TB>>>(p_t, p1, b1);              // h1 packed in P1

    // ---- layer 2: SAGE(mean) + relu ----
    k_sage_mean<<<bNW, TB>>>(p1, p2);                    // agg packed in P2
    k_gemm_bf<128, true, true, true, true, false><<<gGemm, TB>>>(
        p2, p1, pw + 2 * WOFF_WL, pw + 2 * WOFF_WR,
        nullptr, p0, bs, nullptr, nullptr);              // h2 packed in P0

    // ---- layer 3: GAT + relu (alpha fused into GEMM epilogue) ----
    k_gemm_bf<128, false, false, false, false, true><<<gGemm, TB>>>(
        p0, nullptr, pw + 2 * WOFF_WG, nullptr,
        p_agg, nullptr, nullptr, a_s, a_d);              // g fp32 + g_as/g_ad
    k_gat<<<bNW, TB>>>(p_agg, p1, bg);                   // h3 packed in P1

    // ---- layer 4: GCN output ----
    k_gemm_bf<64, false, false, false, false, false><<<gGemm, TB>>>(
        p1, nullptr, pw + 2 * WOFF_WO, nullptr,
        p_t, nullptr, nullptr, nullptr, nullptr);
    k_out_gather<<<bNW, TB>>>(p_t, out, bo);
}

// round 15
// speedup vs baseline: 1.0695x; 1.0454x over previous
#include <cuda_runtime.h>
#include <cuda_bf16.h>
#include <cuda_fp16.h>
#include <math.h>
#include <stdint.h>

#define NN 50000
#define NE 1600000
#define DD 128
#define OO 64

typedef __nv_bfloat16 bf16;
typedef __nv_bfloat162 bf162;

// ---------------- device scratch ----------------
__device__ int   g_is64;
__device__ int   g_deg[NN];
__device__ float g_dinv[NN];
__device__ float g_sinv[NN];
__device__ float g_as[NN];
__device__ float g_ad[NN];
__device__ int   g_rowptr[NN + 1];
__device__ int   g_cur[NN];
__device__ int   g_csr[NE];
// fp16 gather-side feature buffers
__device__ __half g_f16a[(size_t)NN * DD];   // t (L1 out) -> g (L3 out) -> t2 (L4 out)
__device__ __half g_f16b[(size_t)NN * DD];   // h1 fp16 copy for sage gather
// packed split-bf16 feature buffers: 16B group = [hi0..hi3, lo0..lo3] per 4 values
__device__ bf16  g_p0[(size_t)NN * DD * 2];
__device__ bf16  g_p1[(size_t)NN * DD * 2];
__device__ bf16  g_p2[(size_t)NN * DD * 2];
// packed split weights, transposed to [n][k], k=128. Element offsets (x2 for packed).
#define WOFF_W1 0
#define WOFF_WL 16384
#define WOFF_WR 32768
#define WOFF_WG 49152
#define WOFF_WO 65536
#define WTOT    73728
__device__ bf16  g_w[(size_t)WTOT * 2];

__device__ __forceinline__ float leaky(float v) { return v > 0.f ? v : 0.2f * v; }

__device__ __forceinline__ void split2(float x, float y, bf162& hi, bf162& lo) {
    hi = __float22bfloat162_rn(make_float2(x, y));
    lo = __float22bfloat162_rn(make_float2(x - __bfloat162float(hi.x),
                                           y - __bfloat162float(hi.y)));
}

__device__ __forceinline__ void st_packed4(bf16* p, size_t elem_base, float4 v) {
    bf162 h0, l0, h1, l1;
    split2(v.x, v.y, h0, l0);
    split2(v.z, v.w, h1, l1);
    uint4 u;
    u.x = *(uint32_t*)&h0; u.y = *(uint32_t*)&h1;
    u.z = *(uint32_t*)&l0; u.w = *(uint32_t*)&l1;
    *(uint4*)&p[elem_base * 2] = u;
}

__device__ __forceinline__ void st_f16_4(__half* p, size_t base, float4 v) {
    __half2 a = __floats2half2_rn(v.x, v.y);
    __half2 b = __floats2half2_rn(v.z, v.w);
    uint2 u; u.x = *(uint32_t*)&a; u.y = *(uint32_t*)&b;
    *(uint2*)&p[base] = u;
}

__device__ __forceinline__ float4 ld_f16_4(const __half* __restrict__ p, size_t base) {
    uint2 u = *(const uint2*)&p[base];
    __half2 a = *(__half2*)&u.x, b = *(__half2*)&u.y;
    float2 fa = __half22float2(a), fb = __half22float2(b);
    return make_float4(fa.x, fa.y, fb.x, fb.y);
}

__device__ __forceinline__ float2 ld_f16_2(const __half* __restrict__ p, size_t base) {
    uint32_t u = *(const uint32_t*)&p[base];
    __half2 a = *(__half2*)&u;
    return __half22float2(a);
}

__device__ __forceinline__ void edge_ld(const void* ei, int e, int& s, int& d) {
    if (g_is64) {
        const long long* p = (const long long*)ei;
        s = (int)p[e]; d = (int)p[NE + e];
    } else {
        const int* p = (const int*)ei;
        s = p[e]; d = p[NE + e];
    }
}

// ---------------- setup ----------------
__global__ void k_detect_zero(const long long* ei) {
    int i = blockIdx.x * blockDim.x + threadIdx.x;
    if (i == 0) {
        bool is64 = true;
        for (int q = 0; q < 64; q++) {
            long long v = ei[q];
            if (v < 0 || v >= NN) { is64 = false; break; }
        }
        g_is64 = is64 ? 1 : 0;
    }
    if (i < NN) g_deg[i] = 0;
}

__global__ void k_deg(const void* ei) {
    int e = blockIdx.x * blockDim.x + threadIdx.x;
    if (e >= NE) return;
    int d;
    if (g_is64) d = (int)((const long long*)ei)[NE + e];
    else        d = ((const int*)ei)[NE + e];
    atomicAdd(&g_deg[d], 1);
}

__global__ void __launch_bounds__(1024) k_scan_scal() {
    __shared__ int sh[1024];
    __shared__ int sh_carry;
    int tid = threadIdx.x;
    if (tid == 0) { sh_carry = 0; g_rowptr[0] = 0; }
    __syncthreads();
    for (int base = 0; base < NN; base += 1024) {
        int i = base + tid;
        int v = (i < NN) ? g_deg[i] : 0;
        sh[tid] = v;
        __syncthreads();
#pragma unroll
        for (int off = 1; off < 1024; off <<= 1) {
            int t = (tid >= off) ? sh[tid - off] : 0;
            __syncthreads();
            sh[tid] += t;
            __syncthreads();
        }
        int carry = sh_carry;
        if (i < NN) {
            int excl = carry + sh[tid] - v;
            g_rowptr[i + 1] = carry + sh[tid];
            g_cur[i] = excl;
            g_dinv[i] = rsqrtf((float)(v + 1));
            g_sinv[i] = 1.0f / (float)max(v, 1);
        }
        __syncthreads();
        if (tid == 0) sh_carry = carry + sh[1023];
        __syncthreads();
    }
}

__global__ void k_fill(const void* ei) {
    int e = blockIdx.x * blockDim.x + threadIdx.x;
    if (e >= NE) return;
    int s, d; edge_ld(ei, e, s, d);
    int pos = atomicAdd(&g_cur[d], 1);
    g_csr[pos] = s;
}

// ---------------- merged one-shot prep: pack 5 weights (transposed) + x ----------------
__global__ void k_prep(const float* __restrict__ W1, const float* __restrict__ Wl,
                       const float* __restrict__ Wr, const float* __restrict__ Wg,
                       const float* __restrict__ Wo, const float* __restrict__ x,
                       bf16* __restrict__ w, bf16* __restrict__ xp) {
    int i = blockIdx.x * blockDim.x + threadIdx.x;
    if (i < WTOT) {
        const float* src; int N, off, li;
        if (i < 65536) {
            int wi = i >> 14; li = i & 16383; off = wi << 14; N = 128;
            src = (wi == 0) ? W1 : (wi == 1) ? Wl : (wi == 2) ? Wr : Wg;
        } else {
            li = i - 65536; off = 65536; N = 64; src = Wo;
        }
        int k = li / N, n = li % N;
        float v = src[li];
        bf16 hi = __float2bfloat16_rn(v);
        size_t base = (size_t)off * 2 + (size_t)n * 256 + (k >> 2) * 8 + (k & 3);
        w[base]     = hi;
        w[base + 4] = __float2bfloat16_rn(v - __bfloat162float(hi));
    } else {
        int j = i - WTOT;
        if (j < NN * DD / 4) {
            float4 v = ((const float4*)x)[j];
            st_packed4(xp, (size_t)j * 4, v);
        }
    }
}

// ---------------- tensor-core GEMM on packed split bf16 ----------------
__device__ __forceinline__ void mma16816(float* c, const uint32_t* a, const uint32_t* b) {
    asm volatile(
        "mma.sync.aligned.m16n8k16.row.col.f32.bf16.bf16.f32 "
        "{%0,%1,%2,%3}, {%4,%5,%6,%7}, {%8,%9}, {%0,%1,%2,%3};"
        : "+f"(c[0]), "+f"(c[1]), "+f"(c[2]), "+f"(c[3])
        : "r"(a[0]), "r"(a[1]), "r"(a[2]), "r"(a[3]), "r"(b[0]), "r"(b[1]));
}

// C = A@B^T (+A2@B2) (+bias)(relu). A,B packed split bf16.
// OMODE: 0 = fp16 out (Cf), 1 = packed split out (Cp).
// ALPHA: per-row dots with a_s/a_d into g_as/g_ad (BN==128 only).
template<int BN, bool TWO, bool BIAS, bool RELU, int OMODE, bool ALPHA>
__global__ void __launch_bounds__(256) k_gemm_bf(
        const bf16* __restrict__ A1p, const bf16* __restrict__ A2p,
        const bf16* __restrict__ B1p, const bf16* __restrict__ B2p,
        __half* __restrict__ Cf, bf16* __restrict__ Cp,
        const float* __restrict__ bias,
        const float* __restrict__ avs, const float* __restrict__ avd) {
    constexpr int BM = 128, BK = 32, LD = 40;
    constexpr int MWARPS = (BN == 128) ? 2 : 4;
    constexpr int MW = BM / MWARPS;
    constexpr int MT = MW / 16;
    constexpr int NT = 4;

    __shared__ bf16 Ah[BM][LD];
    __shared__ bf16 Al[BM][LD];
    __shared__ bf16 Bh[BN][LD];
    __shared__ bf16 Bl[BN][LD];
    __shared__ float s_as[ALPHA ? BM : 1];
    __shared__ float s_ad[ALPHA ? BM : 1];
    __shared__ float s_avs[ALPHA ? BN : 1];
    __shared__ float s_avd[ALPHA ? BN : 1];

    const int tid = threadIdx.x;
    const int wid = tid >> 5;
    const int lane = tid & 31;
    const int g = lane >> 2;
    const int t = lane & 3;
    const int wm = wid % MWARPS;
    const int wn = wid / MWARPS;
    const int m0 = blockIdx.x * BM;
    const int m0w = wm * MW;
    const int n0w = wn * 32;

    if (ALPHA && tid < BM) {
        s_as[tid] = 0.f; s_ad[tid] = 0.f;
        s_avs[tid] = avs[tid]; s_avd[tid] = avd[tid];
    }

    float c[MT][NT][4];
#pragma unroll
    for (int i = 0; i < MT; i++)
#pragma unroll
        for (int j = 0; j < NT; j++)
#pragma unroll
            for (int q = 0; q < 4; q++) c[i][j][q] = 0.f;

    const int NPH = TWO ? 2 : 1;
    for (int ph = 0; ph < NPH; ph++) {
        const bf16* Ap = (TWO && ph) ? A2p : A1p;
        const bf16* Bp = (TWO && ph) ? B2p : B1p;
#pragma unroll
        for (int k0 = 0; k0 < DD; k0 += BK) {
#pragma unroll
            for (int l = 0; l < 2; l++) {
                int idx = tid + l * 256;
                int m = idx >> 2;
                int ko = (idx & 3) * 8;
                int gr = m0 + m;
                uint4 v0 = make_uint4(0, 0, 0, 0), v1 = make_uint4(0, 0, 0, 0);
                if (gr < NN) {
                    const uint4* p = (const uint4*)&Ap[(size_t)gr * 256 + (k0 + ko) * 2];
                    v0 = p[0]; v1 = p[1];
                }
                *(uint4*)&Ah[m][ko] = make_uint4(v0.x, v0.y, v1.x, v1.y);
                *(uint4*)&Al[m][ko] = make_uint4(v0.z, v0.w, v1.z, v1.w);
            }
            constexpr int NB = (BN * BK) / (8 * 256);
#pragma unroll
            for (int l = 0; l < NB; l++) {
                int idx = tid + l * 256;
                int n = idx >> 2;
                int ko = (idx & 3) * 8;
                const uint4* p = (const uint4*)&Bp[(size_t)n * 256 + (k0 + ko) * 2];
                uint4 v0 = p[0], v1 = p[1];
                *(uint4*)&Bh[n][ko] = make_uint4(v0.x, v0.y, v1.x, v1.y);
                *(uint4*)&Bl[n][ko] = make_uint4(v0.z, v0.w, v1.z, v1.w);
            }
            __syncthreads();
#pragma unroll
            for (int s = 0; s < 2; s++) {
                const int kb = s * 16;
                uint32_t bh[NT][2], bl[NT][2];
#pragma unroll
                for (int nt = 0; nt < NT; nt++) {
                    int nr = n0w + nt * 8 + g;
                    bh[nt][0] = *(const uint32_t*)&Bh[nr][kb + 2 * t];
                    bh[nt][1] = *(const uint32_t*)&Bh[nr][kb + 2 * t + 8];
                    bl[nt][0] = *(const uint32_t*)&Bl[nr][kb + 2 * t];
                    bl[nt][1] = *(const uint32_t*)&Bl[nr][kb + 2 * t + 8];
                }
#pragma unroll
                for (int mt = 0; mt < MT; mt++) {
                    int mr = m0w + mt * 16 + g;
                    uint32_t ah[4], al[4];
                    ah[0] = *(const uint32_t*)&Ah[mr][kb + 2 * t];
                    ah[1] = *(const uint32_t*)&Ah[mr + 8][kb + 2 * t];
                    ah[2] = *(const uint32_t*)&Ah[mr][kb + 2 * t + 8];
                    ah[3] = *(const uint32_t*)&Ah[mr + 8][kb + 2 * t + 8];
                    al[0] = *(const uint32_t*)&Al[mr][kb + 2 * t];
                    al[1] = *(const uint32_t*)&Al[mr + 8][kb + 2 * t];
                    al[2] = *(const uint32_t*)&Al[mr][kb + 2 * t + 8];
                    al[3] = *(const uint32_t*)&Al[mr + 8][kb + 2 * t + 8];
#pragma unroll
                    for (int nt = 0; nt < NT; nt++) {
                        mma16816(c[mt][nt], ah, bh[nt]);
                        mma16816(c[mt][nt], ah, bl[nt]);
                        mma16816(c[mt][nt], al, bh[nt]);
                    }
                }
            }
            __syncthreads();
        }
    }

    // ---- epilogue ----
#pragma unroll
    for (int mt = 0; mt < MT; mt++) {
#pragma unroll
        for (int half = 0; half < 2; half++) {
            int rloc = m0w + mt * 16 + g + half * 8;
            int row = m0 + rloc;
            float ps = 0.f, pd = 0.f;
#pragma unroll
            for (int nt = 0; nt < NT; nt++) {
                int col = n0w + nt * 8 + 2 * t;
                float vx = c[mt][nt][half * 2 + 0];
                float vy = c[mt][nt][half * 2 + 1];
                if (ALPHA) {
                    ps += vx * s_avs[col] + vy * s_avs[col + 1];
                    pd += vx * s_avd[col] + vy * s_avd[col + 1];
                }
                if (BIAS) {
                    float2 b2 = *(const float2*)(bias + col);
                    vx += b2.x; vy += b2.y;
                }
                if (RELU) { vx = fmaxf(vx, 0.f); vy = fmaxf(vy, 0.f); }
                if (row < NN) {
                    if (OMODE == 1) {
                        bf162 hi, lo;
                        split2(vx, vy, hi, lo);
                        size_t gb = (size_t)row * BN * 2 + (col >> 2) * 8 + (col & 3);
                        *(bf162*)&Cp[gb]     = hi;
                        *(bf162*)&Cp[gb + 4] = lo;
                    } else {
                        __half2 hv = __floats2half2_rn(vx, vy);
                        *(__half2*)&Cf[(size_t)row * BN + col] = hv;
                    }
                }
            }
            if (ALPHA) {
                ps += __shfl_xor_sync(0xffffffffu, ps, 1);
                ps += __shfl_xor_sync(0xffffffffu, ps, 2);
                pd += __shfl_xor_sync(0xffffffffu, pd, 1);
                pd += __shfl_xor_sync(0xffffffffu, pd, 2);
                if (t == 0) {
                    atomicAdd(&s_as[rloc], ps);
                    atomicAdd(&s_ad[rloc], pd);
                }
            }
        }
    }
    if (ALPHA) {
        __syncthreads();
        if (tid < BM) {
            int row = m0 + tid;
            if (row < NN) { g_as[row] = s_as[tid]; g_ad[row] = s_ad[tid]; }
        }
    }
}

// ---------------- CSR gather kernels (warp per node, fp16 sources) ----------------
// GCN layer 1: reads fp16 t, writes packed split h1 + fp16 h1
__global__ void k_gcn_gather(const __half* __restrict__ t, bf16* __restrict__ op,
                             __half* __restrict__ of, const float* __restrict__ bias) {
    int w = (blockIdx.x * blockDim.x + threadIdx.x) >> 5;
    int lane = threadIdx.x & 31;
    if (w >= NN) return;
    float di = g_dinv[w];
    int start = g_rowptr[w], end = g_rowptr[w + 1];
    float4 a0 = ld_f16_4(t, (size_t)w * DD + lane * 4);
    float cs = di * di;
    a0.x *= cs; a0.y *= cs; a0.z *= cs; a0.w *= cs;
    float4 a1 = make_float4(0.f, 0.f, 0.f, 0.f);
    float4 a2 = make_float4(0.f, 0.f, 0.f, 0.f);
    float4 a3 = make_float4(0.f, 0.f, 0.f, 0.f);
    int j = start;
    for (; j + 4 <= end; j += 4) {
        int s0 = g_csr[j], s1 = g_csr[j + 1], s2 = g_csr[j + 2], s3 = g_csr[j + 3];
        float c0 = g_dinv[s0] * di, c1 = g_dinv[s1] * di;
        float c2 = g_dinv[s2] * di, c3 = g_dinv[s3] * di;
        float4 v0 = ld_f16_4(t, (size_t)s0 * DD + lane * 4);
        float4 v1 = ld_f16_4(t, (size_t)s1 * DD + lane * 4);
        float4 v2 = ld_f16_4(t, (size_t)s2 * DD + lane * 4);
        float4 v3 = ld_f16_4(t, (size_t)s3 * DD + lane * 4);
        a0.x = fmaf(c0, v0.x, a0.x); a0.y = fmaf(c0, v0.y, a0.y);
        a0.z = fmaf(c0, v0.z, a0.z); a0.w = fmaf(c0, v0.w, a0.w);
        a1.x = fmaf(c1, v1.x, a1.x); a1.y = fmaf(c1, v1.y, a1.y);
        a1.z = fmaf(c1, v1.z, a1.z); a1.w = fmaf(c1, v1.w, a1.w);
        a2.x = fmaf(c2, v2.x, a2.x); a2.y = fmaf(c2, v2.y, a2.y);
        a2.z = fmaf(c2, v2.z, a2.z); a2.w = fmaf(c2, v2.w, a2.w);
        a3.x = fmaf(c3, v3.x, a3.x); a3.y = fmaf(c3, v3.y, a3.y);
        a3.z = fmaf(c3, v3.z, a3.z); a3.w = fmaf(c3, v3.w, a3.w);
    }
    for (; j < end; j++) {
        int s = g_csr[j];
        float cc = g_dinv[s] * di;
        float4 v = ld_f16_4(t, (size_t)s * DD + lane * 4);
        a0.x = fmaf(cc, v.x, a0.x); a0.y = fmaf(cc, v.y, a0.y);
        a0.z = fmaf(cc, v.z, a0.z); a0.w = fmaf(cc, v.w, a0.w);
    }
    a0.x += a1.x + a2.x + a3.x; a0.y += a1.y + a2.y + a3.y;
    a0.z += a1.z + a2.z + a3.z; a0.w += a1.w + a2.w + a3.w;
    float4 b = ((const float4*)bias)[lane];
    a0.x = fmaxf(a0.x + b.x, 0.f); a0.y = fmaxf(a0.y + b.y, 0.f);
    a0.z = fmaxf(a0.z + b.z, 0.f); a0.w = fmaxf(a0.w + b.w, 0.f);
    size_t base = (size_t)w * DD + lane * 4;
    st_packed4(op, base, a0);
    st_f16_4(of, base, a0);
}

// SAGE mean: reads fp16 h1, writes packed
__global__ void k_sage_mean(const __half* __restrict__ hf, bf16* __restrict__ op) {
    int w = (blockIdx.x * blockDim.x + threadIdx.x) >> 5;
    int lane = threadIdx.x & 31;
    if (w >= NN) return;
    int start = g_rowptr[w], end = g_rowptr[w + 1];
    float4 a0 = make_float4(0.f, 0.f, 0.f, 0.f);
    float4 a1 = make_float4(0.f, 0.f, 0.f, 0.f);
    float4 a2 = make_float4(0.f, 0.f, 0.f, 0.f);
    float4 a3 = make_float4(0.f, 0.f, 0.f, 0.f);
    int j = start;
    for (; j + 4 <= end; j += 4) {
        int s0 = g_csr[j], s1 = g_csr[j + 1], s2 = g_csr[j + 2], s3 = g_csr[j + 3];
        float4 v0 = ld_f16_4(hf, (size_t)s0 * DD + lane * 4);
        float4 v1 = ld_f16_4(hf, (size_t)s1 * DD + lane * 4);
        float4 v2 = ld_f16_4(hf, (size_t)s2 * DD + lane * 4);
        float4 v3 = ld_f16_4(hf, (size_t)s3 * DD + lane * 4);
        a0.x += v0.x; a0.y += v0.y; a0.z += v0.z; a0.w += v0.w;
        a1.x += v1.x; a1.y += v1.y; a1.z += v1.z; a1.w += v1.w;
        a2.x += v2.x; a2.y += v2.y; a2.z += v2.z; a2.w += v2.w;
        a3.x += v3.x; a3.y += v3.y; a3.z += v3.z; a3.w += v3.w;
    }
    for (; j < end; j++) {
        int s = g_csr[j];
        float4 v = ld_f16_4(hf, (size_t)s * DD + lane * 4);
        a0.x += v.x; a0.y += v.y; a0.z += v.z; a0.w += v.w;
    }
    float cc = g_sinv[w];
    a0.x = (a0.x + a1.x + a2.x + a3.x) * cc;
    a0.y = (a0.y + a1.y + a2.y + a3.y) * cc;
    a0.z = (a0.z + a1.z + a2.z + a3.z) * cc;
    a0.w = (a0.w + a1.w + a2.w + a3.w) * cc;
    st_packed4(op, (size_t)w * DD + lane * 4, a0);
}

// GAT: reads fp16 g + g_as/g_ad from fused GEMM epilogue, writes packed
__global__ void k_gat(const __half* __restrict__ hf, bf16* __restrict__ op,
                      const float* __restrict__ bias) {
    int w = (blockIdx.x * blockDim.x + threadIdx.x) >> 5;
    int lane = threadIdx.x & 31;
    if (w >= NN) return;
    float ad_d = g_ad[w];
    float as_d = g_as[w];
    int start = g_rowptr[w], end = g_rowptr[w + 1];

    const float NEG = -1e30f;
    float m_l = NEG, s_l = 0.f;
    for (int j = start + lane; j < end; j += 32) {
        int s = g_csr[j];
        float e = leaky(g_as[s] + ad_d);
        if (e > m_l) { s_l *= __expf(m_l - e); m_l = e; }
        s_l += __expf(e - m_l);
    }
#pragma unroll
    for (int off = 16; off > 0; off >>= 1) {
        float m_o = __shfl_xor_sync(0xffffffffu, m_l, off);
        float s_o = __shfl_xor_sync(0xffffffffu, s_l, off);
        float m_n = fmaxf(m_l, m_o);
        s_l = s_l * __expf(m_l - m_n) + s_o * __expf(m_o - m_n);
        m_l = m_n;
    }
    float e_self = leaky(as_d + ad_d);
    float m = fmaxf(m_l, e_self);
    float den = s_l * __expf(m_l - m) + __expf(e_self - m);
    float inv_den = 1.0f / den;

    float wself = __expf(e_self - m) * inv_den;
    float4 a0 = ld_f16_4(hf, (size_t)w * DD + lane * 4);
    a0.x *= wself; a0.y *= wself; a0.z *= wself; a0.w *= wself;
    float4 a1 = make_float4(0.f, 0.f, 0.f, 0.f);
    int j = start;
    for (; j + 2 <= end; j += 2) {
        int s0 = g_csr[j], s1 = g_csr[j + 1];
        float w0 = __expf(leaky(g_as[s0] + ad_d) - m) * inv_den;
        float w1 = __expf(leaky(g_as[s1] + ad_d) - m) * inv_den;
        float4 v0 = ld_f16_4(hf, (size_t)s0 * DD + lane * 4);
        float4 v1 = ld_f16_4(hf, (size_t)s1 * DD + lane * 4);
        a0.x = fmaf(w0, v0.x, a0.x); a0.y = fmaf(w0, v0.y, a0.y);
        a0.z = fmaf(w0, v0.z, a0.z); a0.w = fmaf(w0, v0.w, a0.w);
        a1.x = fmaf(w1, v1.x, a1.x); a1.y = fmaf(w1, v1.y, a1.y);
        a1.z = fmaf(w1, v1.z, a1.z); a1.w = fmaf(w1, v1.w, a1.w);
    }
    if (j < end) {
        int s = g_csr[j];
        float wgt = __expf(leaky(g_as[s] + ad_d) - m) * inv_den;
        float4 v = ld_f16_4(hf, (size_t)s * DD + lane * 4);
        a0.x = fmaf(wgt, v.x, a0.x); a0.y = fmaf(wgt, v.y, a0.y);
        a0.z = fmaf(wgt, v.z, a0.z); a0.w = fmaf(wgt, v.w, a0.w);
    }
    a0.x += a1.x; a0.y += a1.y; a0.z += a1.z; a0.w += a1.w;
    float4 b = ((const float4*)bias)[lane];
    a0.x = fmaxf(a0.x + b.x, 0.f); a0.y = fmaxf(a0.y + b.y, 0.f);
    a0.z = fmaxf(a0.z + b.z, 0.f); a0.w = fmaxf(a0.w + b.w, 0.f);
    st_packed4(op, (size_t)w * DD + lane * 4, a0);
}

// output GCN: reads fp16 t2, writes fp32 out
__global__ void k_out_gather(const __half* __restrict__ t, float* __restrict__ out,
                             const float* __restrict__ bias) {
    int w = (blockIdx.x * blockDim.x + threadIdx.x) >> 5;
    int lane = threadIdx.x & 31;
    if (w >= NN) return;
    float di = g_dinv[w];
    int start = g_rowptr[w], end = g_rowptr[w + 1];
    float2 a0 = ld_f16_2(t, (size_t)w * OO + lane * 2);
    float cs = di * di;
    a0.x *= cs; a0.y *= cs;
    float2 a1 = make_float2(0.f, 0.f);
    float2 a2 = make_float2(0.f, 0.f);
    float2 a3 = make_float2(0.f, 0.f);
    int j = start;
    for (; j + 4 <= end; j += 4) {
        int s0 = g_csr[j], s1 = g_csr[j + 1], s2 = g_csr[j + 2], s3 = g_csr[j + 3];
        float c0 = g_dinv[s0] * di, c1 = g_dinv[s1] * di;
        float c2 = g_dinv[s2] * di, c3 = g_dinv[s3] * di;
        float2 v0 = ld_f16_2(t, (size_t)s0 * OO + lane * 2);
        float2 v1 = ld_f16_2(t, (size_t)s1 * OO + lane * 2);
        float2 v2 = ld_f16_2(t, (size_t)s2 * OO + lane * 2);
        float2 v3 = ld_f16_2(t, (size_t)s3 * OO + lane * 2);
        a0.x = fmaf(c0, v0.x, a0.x); a0.y = fmaf(c0, v0.y, a0.y);
        a1.x = fmaf(c1, v1.x, a1.x); a1.y = fmaf(c1, v1.y, a1.y);
        a2.x = fmaf(c2, v2.x, a2.x); a2.y = fmaf(c2, v2.y, a2.y);
        a3.x = fmaf(c3, v3.x, a3.x); a3.y = fmaf(c3, v3.y, a3.y);
    }
    for (; j < end; j++) {
        int s = g_csr[j];
        float cc = g_dinv[s] * di;
        float2 v = ld_f16_2(t, (size_t)s * OO + lane * 2);
        a0.x = fmaf(cc, v.x, a0.x); a0.y = fmaf(cc, v.y, a0.y);
    }
    float2 b = ((const float2*)bias)[lane];
    a0.x += a1.x + a2.x + a3.x + b.x;
    a0.y += a1.y + a2.y + a3.y + b.y;
    *(float2*)(out + (size_t)w * OO + lane * 2) = a0;
}

// ---------------- launch ----------------
extern "C" void kernel_launch(void* const* d_in, const int* in_sizes, int n_in,
                              void* d_out, int out_size) {
    const float* x  = (const float*)d_in[0];
    const void*  ei = d_in[1];
    const float* W1 = (const float*)d_in[2];
    const float* b1 = (const float*)d_in[3];
    const float* Wl = (const float*)d_in[4];
    const float* Wr = (const float*)d_in[5];
    const float* bs = (const float*)d_in[6];
    const float* Wg = (const float*)d_in[7];
    const float* a_s = (const float*)d_in[8];
    const float* a_d = (const float*)d_in[9];
    const float* bg = (const float*)d_in[10];
    const float* Wo = (const float*)d_in[11];
    const float* bo = (const float*)d_in[12];
    float* out = (float*)d_out;

    __half *fa, *fb;
    bf16 *p0, *p1, *p2, *pw;
    cudaGetSymbolAddress((void**)&fa, g_f16a);
    cudaGetSymbolAddress((void**)&fb, g_f16b);
    cudaGetSymbolAddress((void**)&p0, g_p0);
    cudaGetSymbolAddress((void**)&p1, g_p1);
    cudaGetSymbolAddress((void**)&p2, g_p2);
    cudaGetSymbolAddress((void**)&pw, g_w);

    const int TB = 256;
    const int bN   = (NN + TB - 1) / TB;
    const int bE   = NE / TB;
    const int bNW  = (NN * 32 + TB - 1) / TB;
    const int bPrep = (WTOT + NN * DD / 4 + TB - 1) / TB;
    const int gGemm = (NN + 127) / 128;

    // setup
    k_detect_zero<<<bN, TB>>>((const long long*)ei);
    k_deg<<<bE, TB>>>(ei);
    k_scan_scal<<<1, 1024>>>();
    k_fill<<<bE, TB>>>(ei);
    k_prep<<<bPrep, TB>>>(W1, Wl, Wr, Wg, Wo, x, pw, p0);

    // ---- layer 1: GCN + relu ----
    k_gemm_bf<128, false, false, false, 0, false><<<gGemm, TB>>>(
        p0, nullptr, pw + 2 * WOFF_W1, nullptr,
        fa, nullptr, nullptr, nullptr, nullptr);         // t fp16 in fa
    k_gcn_gather<<<bNW, TB>>>(fa, p1, fb, b1);           // h1 packed P1 + fp16 fb

    // ---- layer 2: SAGE(mean) + relu ----
    k_sage_mean<<<bNW, TB>>>(fb, p2);                    // agg packed P2
    k_gemm_bf<128, true, true, true, 1, false><<<gGemm, TB>>>(
        p2, p1, pw + 2 * WOFF_WL, pw + 2 * WOFF_WR,
        nullptr, p0, bs, nullptr, nullptr);              // h2 packed P0

    // ---- layer 3: GAT + relu (alpha fused into GEMM epilogue) ----
    k_gemm_bf<128, false, false, false, 0, true><<<gGemm, TB>>>(
        p0, nullptr, pw + 2 * WOFF_WG, nullptr,
        fa, nullptr, nullptr, a_s, a_d);                 // g fp16 in fa + g_as/g_ad
    k_gat<<<bNW, TB>>>(fa, p1, bg);                      // h3 packed P1

    // ---- layer 4: GCN output ----
    k_gemm_bf<64, false, false, false, 0, false><<<gGemm, TB>>>(
        p1, nullptr, pw + 2 * WOFF_WO, nullptr,
        fa, nullptr, nullptr, nullptr, nullptr);         // t2 fp16 in fa
    k_out_gather<<<bNW, TB>>>(fa, out, bo);
}

// round 17
// speedup vs baseline: 1.0852x; 1.0147x over previous
#include <cuda_runtime.h>
#include <cuda_bf16.h>
#include <cuda_fp16.h>
#include <math.h>
#include <stdint.h>

#define NN 50000
#define NE 1600000
#define DD 128
#define OO 64

typedef __nv_bfloat16 bf16;
typedef __nv_bfloat162 bf162;

// ---------------- device scratch ----------------
__device__ int   g_is64;
__device__ int   g_deg[NN];
__device__ float g_dinv[NN];
__device__ float g_sinv[NN];
__device__ float g_as[NN];
__device__ float g_ad[NN];
__device__ int   g_rowptr[NN + 1];
__device__ int   g_cur[NN];
__device__ int   g_csr[NE];
// fp16 gather-side feature buffers
__device__ __half g_f16a[(size_t)NN * DD];
__device__ __half g_f16b[(size_t)NN * DD];
// packed split-bf16 feature buffers: 16B group = [hi0..hi3, lo0..lo3] per 4 values
__device__ bf16  g_p0[(size_t)NN * DD * 2];
__device__ bf16  g_p1[(size_t)NN * DD * 2];
__device__ bf16  g_p2[(size_t)NN * DD * 2];
// packed split weights, transposed to [n][k], k=128
#define WOFF_W1 0
#define WOFF_WL 16384
#define WOFF_WR 32768
#define WOFF_WG 49152
#define WOFF_WO 65536
#define WTOT    73728
__device__ bf16  g_w[(size_t)WTOT * 2];

__device__ __forceinline__ float leaky(float v) { return v > 0.f ? v : 0.2f * v; }

__device__ __forceinline__ void split2(float x, float y, bf162& hi, bf162& lo) {
    hi = __float22bfloat162_rn(make_float2(x, y));
    lo = __float22bfloat162_rn(make_float2(x - __bfloat162float(hi.x),
                                           y - __bfloat162float(hi.y)));
}

__device__ __forceinline__ void st_packed4(bf16* p, size_t elem_base, float4 v) {
    bf162 h0, l0, h1, l1;
    split2(v.x, v.y, h0, l0);
    split2(v.z, v.w, h1, l1);
    uint4 u;
    u.x = *(uint32_t*)&h0; u.y = *(uint32_t*)&h1;
    u.z = *(uint32_t*)&l0; u.w = *(uint32_t*)&l1;
    *(uint4*)&p[elem_base * 2] = u;
}

__device__ __forceinline__ void st_f16_4(__half* p, size_t base, float4 v) {
    __half2 a = __floats2half2_rn(v.x, v.y);
    __half2 b = __floats2half2_rn(v.z, v.w);
    uint2 u; u.x = *(uint32_t*)&a; u.y = *(uint32_t*)&b;
    *(uint2*)&p[base] = u;
}

__device__ __forceinline__ float4 ld_f16_4(const __half* __restrict__ p, size_t base) {
    uint2 u = *(const uint2*)&p[base];
    __half2 a = *(__half2*)&u.x, b = *(__half2*)&u.y;
    float2 fa = __half22float2(a), fb = __half22float2(b);
    return make_float4(fa.x, fa.y, fb.x, fb.y);
}

__device__ __forceinline__ float2 ld_f16_2(const __half* __restrict__ p, size_t base) {
    uint32_t u = *(const uint32_t*)&p[base];
    __half2 a = *(__half2*)&u;
    return __half22float2(a);
}

__device__ __forceinline__ void edge_ld(const void* ei, int e, int& s, int& d) {
    if (g_is64) {
        const long long* p = (const long long*)ei;
        s = (int)p[e]; d = (int)p[NE + e];
    } else {
        const int* p = (const int*)ei;
        s = p[e]; d = p[NE + e];
    }
}

// ---------------- setup ----------------
__global__ void k_detect_zero(const long long* ei) {
    int i = blockIdx.x * blockDim.x + threadIdx.x;
    if (i == 0) {
        bool is64 = true;
        for (int q = 0; q < 64; q++) {
            long long v = ei[q];
            if (v < 0 || v >= NN) { is64 = false; break; }
        }
        g_is64 = is64 ? 1 : 0;
    }
    if (i < NN) g_deg[i] = 0;
}

__global__ void k_deg(const void* ei) {
    int e = blockIdx.x * blockDim.x + threadIdx.x;
    if (e >= NE) return;
    int d;
    if (g_is64) d = (int)((const long long*)ei)[NE + e];
    else        d = ((const int*)ei)[NE + e];
    atomicAdd(&g_deg[d], 1);
}

__global__ void __launch_bounds__(1024) k_scan_scal() {
    __shared__ int sh[1024];
    __shared__ int sh_carry;
    int tid = threadIdx.x;
    if (tid == 0) { sh_carry = 0; g_rowptr[0] = 0; }
    __syncthreads();
    for (int base = 0; base < NN; base += 1024) {
        int i = base + tid;
        int v = (i < NN) ? g_deg[i] : 0;
        sh[tid] = v;
        __syncthreads();
#pragma unroll
        for (int off = 1; off < 1024; off <<= 1) {
            int t = (tid >= off) ? sh[tid - off] : 0;
            __syncthreads();
            sh[tid] += t;
            __syncthreads();
        }
        int carry = sh_carry;
        if (i < NN) {
            int excl = carry + sh[tid] - v;
            g_rowptr[i + 1] = carry + sh[tid];
            g_cur[i] = excl;
            g_dinv[i] = rsqrtf((float)(v + 1));
            g_sinv[i] = 1.0f / (float)max(v, 1);
        }
        __syncthreads();
        if (tid == 0) sh_carry = carry + sh[1023];
        __syncthreads();
    }
}

__global__ void k_fill(const void* ei) {
    int e = blockIdx.x * blockDim.x + threadIdx.x;
    if (e >= NE) return;
    int s, d; edge_ld(ei, e, s, d);
    int pos = atomicAdd(&g_cur[d], 1);
    g_csr[pos] = s;
}

// ---------------- merged one-shot prep: pack 5 weights (transposed) + x ----------------
__global__ void k_prep(const float* __restrict__ W1, const float* __restrict__ Wl,
                       const float* __restrict__ Wr, const float* __restrict__ Wg,
                       const float* __restrict__ Wo, const float* __restrict__ x,
                       bf16* __restrict__ w, bf16* __restrict__ xp) {
    int i = blockIdx.x * blockDim.x + threadIdx.x;
    if (i < WTOT) {
        const float* src; int N, off, li;
        if (i < 65536) {
            int wi = i >> 14; li = i & 16383; off = wi << 14; N = 128;
            src = (wi == 0) ? W1 : (wi == 1) ? Wl : (wi == 2) ? Wr : Wg;
        } else {
            li = i - 65536; off = 65536; N = 64; src = Wo;
        }
        int k = li / N, n = li % N;
        float v = src[li];
        bf16 hi = __float2bfloat16_rn(v);
        size_t base = (size_t)off * 2 + (size_t)n * 256 + (k >> 2) * 8 + (k & 3);
        w[base]     = hi;
        w[base + 4] = __float2bfloat16_rn(v - __bfloat162float(hi));
    } else {
        int j = i - WTOT;
        if (j < NN * DD / 4) {
            float4 v = ((const float4*)x)[j];
            st_packed4(xp, (size_t)j * 4, v);
        }
    }
}

// ---------------- tensor-core GEMM on packed split bf16 (software pipelined) ------
__device__ __forceinline__ void mma16816(float* c, const uint32_t* a, const uint32_t* b) {
    asm volatile(
        "mma.sync.aligned.m16n8k16.row.col.f32.bf16.bf16.f32 "
        "{%0,%1,%2,%3}, {%4,%5,%6,%7}, {%8,%9}, {%0,%1,%2,%3};"
        : "+f"(c[0]), "+f"(c[1]), "+f"(c[2]), "+f"(c[3])
        : "r"(a[0]), "r"(a[1]), "r"(a[2]), "r"(a[3]), "r"(b[0]), "r"(b[1]));
}

template<int BN, bool TWO, bool BIAS, bool RELU, int OMODE, bool ALPHA>
__global__ void __launch_bounds__(256) k_gemm_bf(
        const bf16* __restrict__ A1p, const bf16* __restrict__ A2p,
        const bf16* __restrict__ B1p, const bf16* __restrict__ B2p,
        __half* __restrict__ Cf, bf16* __restrict__ Cp,
        const float* __restrict__ bias,
        const float* __restrict__ avs, const float* __restrict__ avd) {
    constexpr int BM = 128, BK = 32, LD = 40;
    constexpr int MWARPS = (BN == 128) ? 2 : 4;
    constexpr int MW = BM / MWARPS;
    constexpr int MT = MW / 16;
    constexpr int NT = 4;
    constexpr int NB = (BN * BK) / (8 * 256);   // 2 or 1
    constexpr int ITOT = (TWO ? 2 : 1) * (DD / BK);

    __shared__ bf16 Ah[BM][LD];
    __shared__ bf16 Al[BM][LD];
    __shared__ bf16 Bh[BN][LD];
    __shared__ bf16 Bl[BN][LD];
    __shared__ float s_as[ALPHA ? BM : 1];
    __shared__ float s_ad[ALPHA ? BM : 1];
    __shared__ float s_avs[ALPHA ? BN : 1];
    __shared__ float s_avd[ALPHA ? BN : 1];

    const int tid = threadIdx.x;
    const int wid = tid >> 5;
    const int lane = tid & 31;
    const int g = lane >> 2;
    const int t = lane & 3;
    const int wm = wid % MWARPS;
    const int wn = wid / MWARPS;
    const int m0 = blockIdx.x * BM;
    const int m0w = wm * MW;
    const int n0w = wn * 32;

    if (ALPHA && tid < BM) {
        s_as[tid] = 0.f; s_ad[tid] = 0.f;
        s_avs[tid] = avs[tid]; s_avd[tid] = avd[tid];
    }

    float c[MT][NT][4];
#pragma unroll
    for (int i = 0; i < MT; i++)
#pragma unroll
        for (int j = 0; j < NT; j++)
#pragma unroll
            for (int q = 0; q < 4; q++) c[i][j][q] = 0.f;

    // prefetch registers
    uint4 ra[2][2];
    uint4 rb[NB][2];

    // ---- global load of tile `it` into regs ----
    auto load_tile = [&](int it) {
        const bf16* Ap = (TWO && (it >= DD / BK)) ? A2p : A1p;
        const bf16* Bp = (TWO && (it >= DD / BK)) ? B2p : B1p;
        int k0 = (it % (DD / BK)) * BK;
#pragma unroll
        for (int l = 0; l < 2; l++) {
            int idx = tid + l * 256;
            int m = idx >> 2;
            int ko = (idx & 3) * 8;
            int gr = m0 + m;
            ra[l][0] = make_uint4(0, 0, 0, 0);
            ra[l][1] = make_uint4(0, 0, 0, 0);
            if (gr < NN) {
                const uint4* p = (const uint4*)&Ap[(size_t)gr * 256 + (k0 + ko) * 2];
                ra[l][0] = p[0]; ra[l][1] = p[1];
            }
        }
#pragma unroll
        for (int l = 0; l < NB; l++) {
            int idx = tid + l * 256;
            int n = idx >> 2;
            int ko = (idx & 3) * 8;
            const uint4* p = (const uint4*)&Bp[(size_t)n * 256 + (k0 + ko) * 2];
            rb[l][0] = p[0]; rb[l][1] = p[1];
        }
    };

    load_tile(0);

#pragma unroll
    for (int it = 0; it < ITOT; it++) {
        // store prefetched regs into smem
#pragma unroll
        for (int l = 0; l < 2; l++) {
            int idx = tid + l * 256;
            int m = idx >> 2;
            int ko = (idx & 3) * 8;
            *(uint4*)&Ah[m][ko] = make_uint4(ra[l][0].x, ra[l][0].y, ra[l][1].x, ra[l][1].y);
            *(uint4*)&Al[m][ko] = make_uint4(ra[l][0].z, ra[l][0].w, ra[l][1].z, ra[l][1].w);
        }
#pragma unroll
        for (int l = 0; l < NB; l++) {
            int idx = tid + l * 256;
            int n = idx >> 2;
            int ko = (idx & 3) * 8;
            *(uint4*)&Bh[n][ko] = make_uint4(rb[l][0].x, rb[l][0].y, rb[l][1].x, rb[l][1].y);
            *(uint4*)&Bl[n][ko] = make_uint4(rb[l][0].z, rb[l][0].w, rb[l][1].z, rb[l][1].w);
        }
        __syncthreads();

        // issue next tile's global loads; they overlap the mma section below
        if (it + 1 < ITOT) load_tile(it + 1);

#pragma unroll
        for (int s = 0; s < 2; s++) {
            const int kb = s * 16;
            uint32_t bh[NT][2], bl[NT][2];
#pragma unroll
            for (int nt = 0; nt < NT; nt++) {
                int nr = n0w + nt * 8 + g;
                bh[nt][0] = *(const uint32_t*)&Bh[nr][kb + 2 * t];
                bh[nt][1] = *(const uint32_t*)&Bh[nr][kb + 2 * t + 8];
                bl[nt][0] = *(const uint32_t*)&Bl[nr][kb + 2 * t];
                bl[nt][1] = *(const uint32_t*)&Bl[nr][kb + 2 * t + 8];
            }
#pragma unroll
            for (int mt = 0; mt < MT; mt++) {
                int mr = m0w + mt * 16 + g;
                uint32_t ah[4], al[4];
                ah[0] = *(const uint32_t*)&Ah[mr][kb + 2 * t];
                ah[1] = *(const uint32_t*)&Ah[mr + 8][kb + 2 * t];
                ah[2] = *(const uint32_t*)&Ah[mr][kb + 2 * t + 8];
                ah[3] = *(const uint32_t*)&Ah[mr + 8][kb + 2 * t + 8];
                al[0] = *(const uint32_t*)&Al[mr][kb + 2 * t];
                al[1] = *(const uint32_t*)&Al[mr + 8][kb + 2 * t];
                al[2] = *(const uint32_t*)&Al[mr][kb + 2 * t + 8];
                al[3] = *(const uint32_t*)&Al[mr + 8][kb + 2 * t + 8];
#pragma unroll
                for (int nt = 0; nt < NT; nt++) {
                    mma16816(c[mt][nt], ah, bh[nt]);
                    mma16816(c[mt][nt], ah, bl[nt]);
                    mma16816(c[mt][nt], al, bh[nt]);
                }
            }
        }
        __syncthreads();
    }

    // ---- epilogue ----
#pragma unroll
    for (int mt = 0; mt < MT; mt++) {
#pragma unroll
        for (int half = 0; half < 2; half++) {
            int rloc = m0w + mt * 16 + g + half * 8;
            int row = m0 + rloc;
            float ps = 0.f, pd = 0.f;
#pragma unroll
            for (int nt = 0; nt < NT; nt++) {
                int col = n0w + nt * 8 + 2 * t;
                float vx = c[mt][nt][half * 2 + 0];
                float vy = c[mt][nt][half * 2 + 1];
                if (ALPHA) {
                    ps += vx * s_avs[col] + vy * s_avs[col + 1];
                    pd += vx * s_avd[col] + vy * s_avd[col + 1];
                }
                if (BIAS) {
                    float2 b2 = *(const float2*)(bias + col);
                    vx += b2.x; vy += b2.y;
                }
                if (RELU) { vx = fmaxf(vx, 0.f); vy = fmaxf(vy, 0.f); }
                if (row < NN) {
                    if (OMODE == 1) {
                        bf162 hi, lo;
                        split2(vx, vy, hi, lo);
                        size_t gb = (size_t)row * BN * 2 + (col >> 2) * 8 + (col & 3);
                        *(bf162*)&Cp[gb]     = hi;
                        *(bf162*)&Cp[gb + 4] = lo;
                    } else {
                        __half2 hv = __floats2half2_rn(vx, vy);
                        *(__half2*)&Cf[(size_t)row * BN + col] = hv;
                    }
                }
            }
            if (ALPHA) {
                ps += __shfl_xor_sync(0xffffffffu, ps, 1);
                ps += __shfl_xor_sync(0xffffffffu, ps, 2);
                pd += __shfl_xor_sync(0xffffffffu, pd, 1);
                pd += __shfl_xor_sync(0xffffffffu, pd, 2);
                if (t == 0) {
                    atomicAdd(&s_as[rloc], ps);
                    atomicAdd(&s_ad[rloc], pd);
                }
            }
        }
    }
    if (ALPHA) {
        __syncthreads();
        if (tid < BM) {
            int row = m0 + tid;
            if (row < NN) { g_as[row] = s_as[tid]; g_ad[row] = s_ad[tid]; }
        }
    }
}

// ---------------- CSR gather kernels (warp per node, fp16 sources) ----------------
__global__ void k_gcn_gather(const __half* __restrict__ t, bf16* __restrict__ op,
                             __half* __restrict__ of, const float* __restrict__ bias) {
    int w = (blockIdx.x * blockDim.x + threadIdx.x) >> 5;
    int lane = threadIdx.x & 31;
    if (w >= NN) return;
    float di = g_dinv[w];
    int start = g_rowptr[w], end = g_rowptr[w + 1];
    float4 a0 = ld_f16_4(t, (size_t)w * DD + lane * 4);
    float cs = di * di;
    a0.x *= cs; a0.y *= cs; a0.z *= cs; a0.w *= cs;
    float4 a1 = make_float4(0.f, 0.f, 0.f, 0.f);
    float4 a2 = make_float4(0.f, 0.f, 0.f, 0.f);
    float4 a3 = make_float4(0.f, 0.f, 0.f, 0.f);
    int j = start;
    for (; j + 4 <= end; j += 4) {
        int s0 = g_csr[j], s1 = g_csr[j + 1], s2 = g_csr[j + 2], s3 = g_csr[j + 3];
        float c0 = g_dinv[s0] * di, c1 = g_dinv[s1] * di;
        float c2 = g_dinv[s2] * di, c3 = g_dinv[s3] * di;
        float4 v0 = ld_f16_4(t, (size_t)s0 * DD + lane * 4);
        float4 v1 = ld_f16_4(t, (size_t)s1 * DD + lane * 4);
        float4 v2 = ld_f16_4(t, (size_t)s2 * DD + lane * 4);
        float4 v3 = ld_f16_4(t, (size_t)s3 * DD + lane * 4);
        a0.x = fmaf(c0, v0.x, a0.x); a0.y = fmaf(c0, v0.y, a0.y);
        a0.z = fmaf(c0, v0.z, a0.z); a0.w = fmaf(c0, v0.w, a0.w);
        a1.x = fmaf(c1, v1.x, a1.x); a1.y = fmaf(c1, v1.y, a1.y);
        a1.z = fmaf(c1, v1.z, a1.z); a1.w = fmaf(c1, v1.w, a1.w);
        a2.x = fmaf(c2, v2.x, a2.x); a2.y = fmaf(c2, v2.y, a2.y);
        a2.z = fmaf(c2, v2.z, a2.z); a2.w = fmaf(c2, v2.w, a2.w);
        a3.x = fmaf(c3, v3.x, a3.x); a3.y = fmaf(c3, v3.y, a3.y);
        a3.z = fmaf(c3, v3.z, a3.z); a3.w = fmaf(c3, v3.w, a3.w);
    }
    for (; j < end; j++) {
        int s = g_csr[j];
        float cc = g_dinv[s] * di;
        float4 v = ld_f16_4(t, (size_t)s * DD + lane * 4);
        a0.x = fmaf(cc, v.x, a0.x); a0.y = fmaf(cc, v.y, a0.y);
        a0.z = fmaf(cc, v.z, a0.z); a0.w = fmaf(cc, v.w, a0.w);
    }
    a0.x += a1.x + a2.x + a3.x; a0.y += a1.y + a2.y + a3.y;
    a0.z += a1.z + a2.z + a3.z; a0.w += a1.w + a2.w + a3.w;
    float4 b = ((const float4*)bias)[lane];
    a0.x = fmaxf(a0.x + b.x, 0.f); a0.y = fmaxf(a0.y + b.y, 0.f);
    a0.z = fmaxf(a0.z + b.z, 0.f); a0.w = fmaxf(a0.w + b.w, 0.f);
    size_t base = (size_t)w * DD + lane * 4;
    st_packed4(op, base, a0);
    st_f16_4(of, base, a0);
}

__global__ void k_sage_mean(const __half* __restrict__ hf, bf16* __restrict__ op) {
    int w = (blockIdx.x * blockDim.x + threadIdx.x) >> 5;
    int lane = threadIdx.x & 31;
    if (w >= NN) return;
    int start = g_rowptr[w], end = g_rowptr[w + 1];
    float4 a0 = make_float4(0.f, 0.f, 0.f, 0.f);
    float4 a1 = make_float4(0.f, 0.f, 0.f, 0.f);
    float4 a2 = make_float4(0.f, 0.f, 0.f, 0.f);
    float4 a3 = make_float4(0.f, 0.f, 0.f, 0.f);
    int j = start;
    for (; j + 4 <= end; j += 4) {
        int s0 = g_csr[j], s1 = g_csr[j + 1], s2 = g_csr[j + 2], s3 = g_csr[j + 3];
        float4 v0 = ld_f16_4(hf, (size_t)s0 * DD + lane * 4);
        float4 v1 = ld_f16_4(hf, (size_t)s1 * DD + lane * 4);
        float4 v2 = ld_f16_4(hf, (size_t)s2 * DD + lane * 4);
        float4 v3 = ld_f16_4(hf, (size_t)s3 * DD + lane * 4);
        a0.x += v0.x; a0.y += v0.y; a0.z += v0.z; a0.w += v0.w;
        a1.x += v1.x; a1.y += v1.y; a1.z += v1.z; a1.w += v1.w;
        a2.x += v2.x; a2.y += v2.y; a2.z += v2.z; a2.w += v2.w;
        a3.x += v3.x; a3.y += v3.y; a3.z += v3.z; a3.w += v3.w;
    }
    for (; j < end; j++) {
        int s = g_csr[j];
        float4 v = ld_f16_4(hf, (size_t)s * DD + lane * 4);
        a0.x += v.x; a0.y += v.y; a0.z += v.z; a0.w += v.w;
    }
    float cc = g_sinv[w];
    a0.x = (a0.x + a1.x + a2.x + a3.x) * cc;
    a0.y = (a0.y + a1.y + a2.y + a3.y) * cc;
    a0.z = (a0.z + a1.z + a2.z + a3.z) * cc;
    a0.w = (a0.w + a1.w + a2.w + a3.w) * cc;
    st_packed4(op, (size_t)w * DD + lane * 4, a0);
}

// GAT: unroll-4 weighted gather
__global__ void k_gat(const __half* __restrict__ hf, bf16* __restrict__ op,
                      const float* __restrict__ bias) {
    int w = (blockIdx.x * blockDim.x + threadIdx.x) >> 5;
    int lane = threadIdx.x & 31;
    if (w >= NN) return;
    float ad_d = g_ad[w];
    float as_d = g_as[w];
    int start = g_rowptr[w], end = g_rowptr[w + 1];

    const float NEG = -1e30f;
    float m_l = NEG, s_l = 0.f;
    for (int j = start + lane; j < end; j += 32) {
        int s = g_csr[j];
        float e = leaky(g_as[s] + ad_d);
        if (e > m_l) { s_l *= __expf(m_l - e); m_l = e; }
        s_l += __expf(e - m_l);
    }
#pragma unroll
    for (int off = 16; off > 0; off >>= 1) {
        float m_o = __shfl_xor_sync(0xffffffffu, m_l, off);
        float s_o = __shfl_xor_sync(0xffffffffu, s_l, off);
        float m_n = fmaxf(m_l, m_o);
        s_l = s_l * __expf(m_l - m_n) + s_o * __expf(m_o - m_n);
        m_l = m_n;
    }
    float e_self = leaky(as_d + ad_d);
    float m = fmaxf(m_l, e_self);
    float den = s_l * __expf(m_l - m) + __expf(e_self - m);
    float inv_den = 1.0f / den;

    float wself = __expf(e_self - m) * inv_den;
    float4 a0 = ld_f16_4(hf, (size_t)w * DD + lane * 4);
    a0.x *= wself; a0.y *= wself; a0.z *= wself; a0.w *= wself;
    float4 a1 = make_float4(0.f, 0.f, 0.f, 0.f);
    float4 a2 = make_float4(0.f, 0.f, 0.f, 0.f);
    float4 a3 = make_float4(0.f, 0.f, 0.f, 0.f);
    int j = start;
    for (; j + 4 <= end; j += 4) {
        int s0 = g_csr[j], s1 = g_csr[j + 1], s2 = g_csr[j + 2], s3 = g_csr[j + 3];
        float w0 = __expf(leaky(g_as[s0] + ad_d) - m) * inv_den;
        float w1 = __expf(leaky(g_as[s1] + ad_d) - m) * inv_den;
        float w2 = __expf(leaky(g_as[s2] + ad_d) - m) * inv_den;
        float w3 = __expf(leaky(g_as[s3] + ad_d) - m) * inv_den;
        float4 v0 = ld_f16_4(hf, (size_t)s0 * DD + lane * 4);
        float4 v1 = ld_f16_4(hf, (size_t)s1 * DD + lane * 4);
        float4 v2 = ld_f16_4(hf, (size_t)s2 * DD + lane * 4);
        float4 v3 = ld_f16_4(hf, (size_t)s3 * DD + lane * 4);
        a0.x = fmaf(w0, v0.x, a0.x); a0.y = fmaf(w0, v0.y, a0.y);
        a0.z = fmaf(w0, v0.z, a0.z); a0.w = fmaf(w0, v0.w, a0.w);
        a1.x = fmaf(w1, v1.x, a1.x); a1.y = fmaf(w1, v1.y, a1.y);
        a1.z = fmaf(w1, v1.z, a1.z); a1.w = fmaf(w1, v1.w, a1.w);
        a2.x = fmaf(w2, v2.x, a2.x); a2.y = fmaf(w2, v2.y, a2.y);
        a2.z = fmaf(w2, v2.z, a2.z); a2.w = fmaf(w2, v2.w, a2.w);
        a3.x = fmaf(w3, v3.x, a3.x); a3.y = fmaf(w3, v3.y, a3.y);
        a3.z = fmaf(w3, v3.z, a3.z); a3.w = fmaf(w3, v3.w, a3.w);
    }
    for (; j < end; j++) {
        int s = g_csr[j];
        float wgt = __expf(leaky(g_as[s] + ad_d) - m) * inv_den;
        float4 v = ld_f16_4(hf, (size_t)s * DD + lane * 4);
        a0.x = fmaf(wgt, v.x, a0.x); a0.y = fmaf(wgt, v.y, a0.y);
        a0.z = fmaf(wgt, v.z, a0.z); a0.w = fmaf(wgt, v.w, a0.w);
    }
    a0.x += a1.x + a2.x + a3.x; a0.y += a1.y + a2.y + a3.y;
    a0.z += a1.z + a2.z + a3.z; a0.w += a1.w + a2.w + a3.w;
    float4 b = ((const float4*)bias)[lane];
    a0.x = fmaxf(a0.x + b.x, 0.f); a0.y = fmaxf(a0.y + b.y, 0.f);
    a0.z = fmaxf(a0.z + b.z, 0.f); a0.w = fmaxf(a0.w + b.w, 0.f);
    st_packed4(op, (size_t)w * DD + lane * 4, a0);
}

__global__ void k_out_gather(const __half* __restrict__ t, float* __restrict__ out,
                             const float* __restrict__ bias) {
    int w = (blockIdx.x * blockDim.x + threadIdx.x) >> 5;
    int lane = threadIdx.x & 31;
    if (w >= NN) return;
    float di = g_dinv[w];
    int start = g_rowptr[w], end = g_rowptr[w + 1];
    float2 a0 = ld_f16_2(t, (size_t)w * OO + lane * 2);
    float cs = di * di;
    a0.x *= cs; a0.y *= cs;
    float2 a1 = make_float2(0.f, 0.f);
    float2 a2 = make_float2(0.f, 0.f);
    float2 a3 = make_float2(0.f, 0.f);
    int j = start;
    for (; j + 4 <= end; j += 4) {
        int s0 = g_csr[j], s1 = g_csr[j + 1], s2 = g_csr[j + 2], s3 = g_csr[j + 3];
        float c0 = g_dinv[s0] * di, c1 = g_dinv[s1] * di;
        float c2 = g_dinv[s2] * di, c3 = g_dinv[s3] * di;
        float2 v0 = ld_f16_2(t, (size_t)s0 * OO + lane * 2);
        float2 v1 = ld_f16_2(t, (size_t)s1 * OO + lane * 2);
        float2 v2 = ld_f16_2(t, (size_t)s2 * OO + lane * 2);
        float2 v3 = ld_f16_2(t, (size_t)s3 * OO + lane * 2);
        a0.x = fmaf(c0, v0.x, a0.x); a0.y = fmaf(c0, v0.y, a0.y);
        a1.x = fmaf(c1, v1.x, a1.x); a1.y = fmaf(c1, v1.y, a1.y);
        a2.x = fmaf(c2, v2.x, a2.x); a2.y = fmaf(c2, v2.y, a2.y);
        a3.x = fmaf(c3, v3.x, a3.x); a3.y = fmaf(c3, v3.y, a3.y);
    }
    for (; j < end; j++) {
        int s = g_csr[j];
        float cc = g_dinv[s] * di;
        float2 v = ld_f16_2(t, (size_t)s * OO + lane * 2);
        a0.x = fmaf(cc, v.x, a0.x); a0.y = fmaf(cc, v.y, a0.y);
    }
    float2 b = ((const float2*)bias)[lane];
    a0.x += a1.x + a2.x + a3.x + b.x;
    a0.y += a1.y + a2.y + a3.y + b.y;
    *(float2*)(out + (size_t)w * OO + lane * 2) = a0;
}

// ---------------- launch ----------------
extern "C" void kernel_launch(void* const* d_in, const int* in_sizes, int n_in,
                              void* d_out, int out_size) {
    const float* x  = (const float*)d_in[0];
    const void*  ei = d_in[1];
    const float* W1 = (const float*)d_in[2];
    const float* b1 = (const float*)d_in[3];
    const float* Wl = (const float*)d_in[4];
    const float* Wr = (const float*)d_in[5];
    const float* bs = (const float*)d_in[6];
    const float* Wg = (const float*)d_in[7];
    const float* a_s = (const float*)d_in[8];
    const float* a_d = (const float*)d_in[9];
    const float* bg = (const float*)d_in[10];
    const float* Wo = (const float*)d_in[11];
    const float* bo = (const float*)d_in[12];
    float* out = (float*)d_out;

    __half *fa, *fb;
    bf16 *p0, *p1, *p2, *pw;
    cudaGetSymbolAddress((void**)&fa, g_f16a);
    cudaGetSymbolAddress((void**)&fb, g_f16b);
    cudaGetSymbolAddress((void**)&p0, g_p0);
    cudaGetSymbolAddress((void**)&p1, g_p1);
    cudaGetSymbolAddress((void**)&p2, g_p2);
    cudaGetSymbolAddress((void**)&pw, g_w);

    const int TB = 256;
    const int bN   = (NN + TB - 1) / TB;
    const int bE   = NE / TB;
    const int bNW  = (NN * 32 + TB - 1) / TB;
    const int bPrep = (WTOT + NN * DD / 4 + TB - 1) / TB;
    const int gGemm = (NN + 127) / 128;

    // setup
    k_detect_zero<<<bN, TB>>>((const long long*)ei);
    k_deg<<<bE, TB>>>(ei);
    k_scan_scal<<<1, 1024>>>();
    k_fill<<<bE, TB>>>(ei);
    k_prep<<<bPrep, TB>>>(W1, Wl, Wr, Wg, Wo, x, pw, p0);

    // ---- layer 1: GCN + relu ----
    k_gemm_bf<128, false, false, false, 0, false><<<gGemm, TB>>>(
        p0, nullptr, pw + 2 * WOFF_W1, nullptr,
        fa, nullptr, nullptr, nullptr, nullptr);
    k_gcn_gather<<<bNW, TB>>>(fa, p1, fb, b1);

    // ---- layer 2: SAGE(mean) + relu ----
    k_sage_mean<<<bNW, TB>>>(fb, p2);
    k_gemm_bf<128, true, true, true, 1, false><<<gGemm, TB>>>(
        p2, p1, pw + 2 * WOFF_WL, pw + 2 * WOFF_WR,
        nullptr, p0, bs, nullptr, nullptr);

    // ---- layer 3: GAT + relu (alpha fused into GEMM epilogue) ----
    k_gemm_bf<128, false, false, false, 0, true><<<gGemm, TB>>>(
        p0, nullptr, pw + 2 * WOFF_WG, nullptr,
        fa, nullptr, nullptr, a_s, a_d);
    k_gat<<<bNW, TB>>>(fa, p1, bg);

    // ---- layer 4: GCN output ----
    k_gemm_bf<64, false, false, false, 0, false><<<gGemm, TB>>>(
        p1, nullptr, pw + 2 * WOFF_WO, nullptr,
        fa, nullptr, nullptr, nullptr, nullptr);
    k_out_gather<<<bNW, TB>>>(fa, out, bo);
}